// round 4
// baseline (speedup 1.0000x reference)
#include <cuda_runtime.h>
#include <cuda_bf16.h>
#include <cstdint>
#include <math.h>

// ---------------- problem constants ----------------
#define Bn   16
#define Hh   56
#define Ww   56
#define HW   (Hh*Ww)          // 3136
#define NROW (Bn*HW)          // 50176
#define CIN  384
#define NF   384
#define KK   3
#define D1   (NF*KK)          // 1152

// ---------------- device scratch ----------------
__device__ float          g_y[(size_t)NROW * D1];       // 231 MB fp32 y
__device__ __nv_bfloat16  g_xh[(size_t)NROW * CIN];
__device__ __nv_bfloat16  g_xl[(size_t)NROW * CIN];
__device__ __nv_bfloat16  g_oh[(size_t)NROW * NF];
__device__ __nv_bfloat16  g_ol[(size_t)NROW * NF];
__device__ __nv_bfloat16  g_w1h[(size_t)D1 * CIN];      // W1^T [N,K]
__device__ __nv_bfloat16  g_w1l[(size_t)D1 * CIN];
__device__ __nv_bfloat16  g_w2h[(size_t)NF * NF];       // W2^T [N,K]
__device__ __nv_bfloat16  g_w2l[(size_t)NF * NF];
__device__ float g_a[Bn * NF];
__device__ float g_abar[Bn * D1];

// ---------------- helpers ----------------
__device__ __forceinline__ uint32_t smem_u32(const void* p) {
    uint32_t a;
    asm("{ .reg .u64 t; cvta.to.shared.u64 t, %1; cvt.u32.u64 %0, t; }" : "=r"(a) : "l"(p));
    return a;
}
__device__ __forceinline__ void cp16(uint32_t s, const void* g) {
    asm volatile("cp.async.cg.shared.global [%0], [%1], 16;" :: "r"(s), "l"(g));
}
__device__ __forceinline__ void ldsm_x4(uint32_t& r0, uint32_t& r1, uint32_t& r2,
                                        uint32_t& r3, uint32_t addr) {
    asm volatile("ldmatrix.sync.aligned.m8n8.x4.shared.b16 {%0,%1,%2,%3}, [%4];"
                 : "=r"(r0), "=r"(r1), "=r"(r2), "=r"(r3) : "r"(addr));
}
__device__ __forceinline__ void mma_bf16(float* d, const uint32_t* a,
                                         uint32_t b0, uint32_t b1) {
    asm volatile("mma.sync.aligned.m16n8k16.row.col.f32.bf16.bf16.f32 "
        "{%0,%1,%2,%3}, {%4,%5,%6,%7}, {%8,%9}, {%0,%1,%2,%3};"
        : "+f"(d[0]), "+f"(d[1]), "+f"(d[2]), "+f"(d[3])
        : "r"(a[0]), "r"(a[1]), "r"(a[2]), "r"(a[3]), "r"(b0), "r"(b1));
}

// ---------------- bf16-split HMMA GEMM ----------------
// C[M,N] = (Ah+Al)[M,K] @ (Bh+Bl)[N,K]^T + bias; drop Al*Bl.
// CTA tile 128x128x32, 8 warps (2x4), warp tile 64x32.
#define BM 128
#define BN 128
#define BK 32
#define PITCH 80
#define T_BYTES (128 * PITCH)
#define OFF_AH 0
#define OFF_AL (T_BYTES)
#define OFF_BH (2 * T_BYTES)
#define OFF_BL (3 * T_BYTES)
#define STAGE_BYTES (4 * T_BYTES)  // 40960
#define GEMM_SMEM (2 * STAGE_BYTES)

__device__ __forceinline__ void load_stage(
    uint32_t stg, const __nv_bfloat16* Ah, const __nv_bfloat16* Al,
    const __nv_bfloat16* Bh, const __nv_bfloat16* Bl,
    int bm0, int bn0, int k0, int K, int tid)
{
    #pragma unroll
    for (int t = 0; t < 2; ++t) {
        int idx = tid + t * 256;
        int r = idx >> 2, c = idx & 3;
        uint32_t so = r * PITCH + c * 16;
        size_t ga = (size_t)(bm0 + r) * K + k0 + c * 8;
        cp16(stg + OFF_AH + so, Ah + ga);
        cp16(stg + OFF_AL + so, Al + ga);
        size_t gb = (size_t)(bn0 + r) * K + k0 + c * 8;
        cp16(stg + OFF_BH + so, Bh + gb);
        cp16(stg + OFF_BL + so, Bl + gb);
    }
}

__global__ __launch_bounds__(256)
void gemm_bf16split(const __nv_bfloat16* __restrict__ Ah,
                    const __nv_bfloat16* __restrict__ Al,
                    const __nv_bfloat16* __restrict__ Bh,
                    const __nv_bfloat16* __restrict__ Bl,
                    const float* __restrict__ bias,
                    float* __restrict__ C, int M, int N, int K)
{
    extern __shared__ char smem[];
    const uint32_t sbase = smem_u32(smem);
    const int tid = threadIdx.x, wid = tid >> 5, lane = tid & 31;
    const int warp_m = wid >> 2, warp_n = wid & 3;      // 2 x 4
    const int bn0 = blockIdx.x * BN, bm0 = blockIdx.y * BM;
    const int NC = K / BK;                               // 12

    float acc[4][4][4] = {};

    const int a_r = (lane & 15);
    const int a_kb = ((lane >> 4) << 3) * 2;
    const int b_r = ((lane >> 4) << 3) + (lane & 7);
    const int b_kb = (((lane >> 3) & 1) << 3) * 2;

    load_stage(sbase, Ah, Al, Bh, Bl, bm0, bn0, 0, K, tid);
    asm volatile("cp.async.commit_group;" ::: "memory");

    for (int c = 0; c < NC; ++c) {
        if (c + 1 < NC) {
            load_stage(sbase + ((c + 1) & 1) * STAGE_BYTES,
                       Ah, Al, Bh, Bl, bm0, bn0, (c + 1) * BK, K, tid);
            asm volatile("cp.async.commit_group;" ::: "memory");
            asm volatile("cp.async.wait_group 1;" ::: "memory");
        } else {
            asm volatile("cp.async.wait_group 0;" ::: "memory");
        }
        __syncthreads();

        const uint32_t stg = sbase + (c & 1) * STAGE_BYTES;
        #pragma unroll
        for (int ks = 0; ks < 2; ++ks) {
            const int koff = ks * 32;
            uint32_t ah[4][4], al[4][4], bh[2][4], bl[2][4];
            #pragma unroll
            for (int i = 0; i < 4; ++i) {
                uint32_t ra = (warp_m * 64 + i * 16 + a_r) * PITCH + koff + a_kb;
                ldsm_x4(ah[i][0], ah[i][1], ah[i][2], ah[i][3], stg + OFF_AH + ra);
                ldsm_x4(al[i][0], al[i][1], al[i][2], al[i][3], stg + OFF_AL + ra);
            }
            #pragma unroll
            for (int jp = 0; jp < 2; ++jp) {
                uint32_t rb = (warp_n * 32 + jp * 16 + b_r) * PITCH + koff + b_kb;
                ldsm_x4(bh[jp][0], bh[jp][1], bh[jp][2], bh[jp][3], stg + OFF_BH + rb);
                ldsm_x4(bl[jp][0], bl[jp][1], bl[jp][2], bl[jp][3], stg + OFF_BL + rb);
            }
            // Product-major ordering: every consecutive MMA targets a DIFFERENT
            // accumulator -> dependency distance 16 instead of 1.
            #pragma unroll
            for (int i = 0; i < 4; ++i)
                #pragma unroll
                for (int j = 0; j < 4; ++j) {
                    const int jp = j >> 1, jj = j & 1;
                    mma_bf16(acc[i][j], ah[i], bh[jp][jj * 2], bh[jp][jj * 2 + 1]);
                }
            #pragma unroll
            for (int i = 0; i < 4; ++i)
                #pragma unroll
                for (int j = 0; j < 4; ++j) {
                    const int jp = j >> 1, jj = j & 1;
                    mma_bf16(acc[i][j], ah[i], bl[jp][jj * 2], bl[jp][jj * 2 + 1]);
                }
            #pragma unroll
            for (int i = 0; i < 4; ++i)
                #pragma unroll
                for (int j = 0; j < 4; ++j) {
                    const int jp = j >> 1, jj = j & 1;
                    mma_bf16(acc[i][j], al[i], bh[jp][jj * 2], bh[jp][jj * 2 + 1]);
                }
        }
        __syncthreads();
    }

    #pragma unroll
    for (int i = 0; i < 4; ++i) {
        int row0 = bm0 + warp_m * 64 + i * 16 + (lane >> 2);
        #pragma unroll
        for (int j = 0; j < 4; ++j) {
            int col = bn0 + warp_n * 32 + j * 8 + (lane & 3) * 2;
            float b0 = bias[col], b1 = bias[col + 1];
            float2 v0 = {acc[i][j][0] + b0, acc[i][j][1] + b1};
            float2 v1 = {acc[i][j][2] + b0, acc[i][j][3] + b1};
            *reinterpret_cast<float2*>(C + (size_t)row0 * N + col) = v0;
            *reinterpret_cast<float2*>(C + (size_t)(row0 + 8) * N + col) = v1;
        }
    }
}

// ---------------- conversion kernels ----------------
__device__ __forceinline__ void split1(float v, __nv_bfloat16& h, __nv_bfloat16& l) {
    h = __float2bfloat16_rn(v);
    l = __float2bfloat16_rn(v - __bfloat162float(h));
}

__global__ __launch_bounds__(256)
void split_pair_kernel(const float* __restrict__ src,
                       __nv_bfloat16* __restrict__ h, __nv_bfloat16* __restrict__ l, int n4) {
    int i = blockIdx.x * blockDim.x + threadIdx.x;
    if (i >= n4) return;
    float4 v = reinterpret_cast<const float4*>(src)[i];
    __nv_bfloat16 h0, h1, h2, h3, l0, l1, l2, l3;
    split1(v.x, h0, l0); split1(v.y, h1, l1); split1(v.z, h2, l2); split1(v.w, h3, l3);
    __nv_bfloat162* hp = reinterpret_cast<__nv_bfloat162*>(h);
    __nv_bfloat162* lp = reinterpret_cast<__nv_bfloat162*>(l);
    hp[2 * i]     = __nv_bfloat162{h0, h1};
    hp[2 * i + 1] = __nv_bfloat162{h2, h3};
    lp[2 * i]     = __nv_bfloat162{l0, l1};
    lp[2 * i + 1] = __nv_bfloat162{l2, l3};
}

__global__ void wsplit_kernel(const float* __restrict__ W,
                              __nv_bfloat16* __restrict__ Oh, __nv_bfloat16* __restrict__ Ol,
                              int K, int N) {
    __shared__ float t[32][33];
    int n0 = blockIdx.x * 32, k0 = blockIdx.y * 32;
    int tx = threadIdx.x, ty = threadIdx.y;
    #pragma unroll
    for (int r = 0; r < 4; r++)
        t[ty + 8 * r][tx] = W[(size_t)(k0 + ty + 8 * r) * N + n0 + tx];
    __syncthreads();
    #pragma unroll
    for (int r = 0; r < 4; r++) {
        int n = n0 + ty + 8 * r, k = k0 + tx;
        float v = t[tx][ty + 8 * r];
        __nv_bfloat16 h, l; split1(v, h, l);
        Oh[(size_t)n * K + k] = h;
        Ol[(size_t)n * K + k] = l;
    }
}

// ---------------- shift / gating path ----------------
__device__ __forceinline__ int shift_src(int mode, int q, int h, int w) {
    int hh = h, ww = w;
    if (mode == 1) {
        if      (q == 0) ww = max(w - 1, 0);
        else if (q == 1) ww = min(w + 1, Ww - 1);
        else if (q == 2) hh = max(h - 1, 0);
        else             hh = min(h + 1, Hh - 1);
    } else {
        if      (q == 0) hh = max(h - 1, 0);
        else if (q == 1) hh = min(h + 1, Hh - 1);
        else if (q == 2) ww = max(w - 1, 0);
        else             ww = min(w + 1, Ww - 1);
    }
    return hh * Ww + ww;
}

__global__ void zero_a_kernel() {
    int i = blockIdx.x * blockDim.x + threadIdx.x;
    if (i < Bn * NF) g_a[i] = 0.0f;
}

__global__ __launch_bounds__(384)
void reduce_a_kernel() {
    const int b = blockIdx.y, chunk = blockIdx.x, c = threadIdx.x;
    const int q = c / (NF / 4);
    const float* yb = g_y + (size_t)b * HW * D1;
    float acc = 0.0f;
    for (int j = 0; j < 64; j++) {
        int hw = chunk * 64 + j;
        int h = hw / Ww, w = hw % Ww;
        int s1 = shift_src(1, q, h, w);
        int s2 = shift_src(2, q, h, w);
        acc += yb[(size_t)s1 * D1 + c]
             + yb[(size_t)s2 * D1 + NF + c]
             + yb[(size_t)hw * D1 + 2 * NF + c];
    }
    atomicAdd(&g_a[b * NF + c], acc);
}

__device__ __forceinline__ float gelu_t(float x) {
    float t = tanhf(0.7978845608028654f * (x + 0.044715f * x * x * x));
    return 0.5f * x * (1.0f + t);
}

// Fused gating: h = gelu(a@Wg1); ahat = h@Wg2; abar = softmax_K(ahat).
// 768 threads: 2-way split of the reduction dim, smem combine.
__global__ __launch_bounds__(768)
void gating_kernel(const float* __restrict__ Wg1, const float* __restrict__ Wg2) {
    __shared__ float a_s[NF];
    __shared__ float h_s[NF];
    __shared__ float part[2][NF];
    const int b = blockIdx.x;
    const int tid = threadIdx.x;
    const int c = tid & (NF - 1);      // NF=384 not pow2 -> use explicit split
    const int half = tid / NF;         // 0 or 1
    const int cc = tid - half * NF;    // channel
    if (tid < NF) a_s[tid] = g_a[b * NF + tid];
    __syncthreads();

    // h = gelu(a @ Wg1)
    {
        float s = 0.0f;
        const int i0 = half * (NF / 2);
        #pragma unroll 16
        for (int j = 0; j < NF / 2; j++)
            s += a_s[i0 + j] * Wg1[(size_t)(i0 + j) * NF + cc];
        part[half][cc] = s;
    }
    __syncthreads();
    if (tid < NF) h_s[tid] = gelu_t(part[0][tid] + part[1][tid]);
    __syncthreads();

    // ahat = h @ Wg2, then softmax over K
    float s0 = 0.0f, s1 = 0.0f, s2 = 0.0f;
    {
        const int i0 = half * (NF / 2);
        #pragma unroll 8
        for (int j = 0; j < NF / 2; j++) {
            float hv = h_s[i0 + j];
            const float* w = Wg2 + (size_t)(i0 + j) * D1 + cc;
            s0 += hv * w[0];
            s1 += hv * w[NF];
            s2 += hv * w[2 * NF];
        }
    }
    part[half][cc] = s0; __syncthreads();
    float a0 = (tid < NF) ? part[0][tid] + part[1][tid] : 0.0f; __syncthreads();
    part[half][cc] = s1; __syncthreads();
    float a1 = (tid < NF) ? part[0][tid] + part[1][tid] : 0.0f; __syncthreads();
    part[half][cc] = s2; __syncthreads();
    float a2 = (tid < NF) ? part[0][tid] + part[1][tid] : 0.0f;

    if (tid < NF) {
        float m = fmaxf(a0, fmaxf(a1, a2));
        float e0 = expf(a0 - m), e1 = expf(a1 - m), e2 = expf(a2 - m);
        float inv = 1.0f / (e0 + e1 + e2);
        g_abar[b * D1 + tid] = e0 * inv;
        g_abar[b * D1 + NF + tid] = e1 * inv;
        g_abar[b * D1 + 2 * NF + tid] = e2 * inv;
    }
    (void)c;
}

__global__ __launch_bounds__(384)
void combine_kernel() {
    __shared__ float ab[D1];
    const int b = blockIdx.y, chunk = blockIdx.x, c = threadIdx.x;
    for (int i = c; i < D1; i += NF) ab[i] = g_abar[b * D1 + i];
    __syncthreads();

    const int q = c / (NF / 4);
    const float a0 = ab[c], a1 = ab[NF + c], a2 = ab[2 * NF + c];
    const float* yb = g_y + (size_t)b * HW * D1;
    __nv_bfloat16* oh = g_oh + (size_t)b * HW * NF;
    __nv_bfloat16* ol = g_ol + (size_t)b * HW * NF;

    for (int j = 0; j < 64; j++) {
        int hw = chunk * 64 + j;
        int h = hw / Ww, w = hw % Ww;
        int s1 = shift_src(1, q, h, w);
        int s2 = shift_src(2, q, h, w);
        float v = a0 * yb[(size_t)s1 * D1 + c]
                + a1 * yb[(size_t)s2 * D1 + NF + c]
                + a2 * yb[(size_t)hw * D1 + 2 * NF + c];
        __nv_bfloat16 hv, lv; split1(v, hv, lv);
        oh[(size_t)hw * NF + c] = hv;
        ol[(size_t)hw * NF + c] = lv;
    }
}

// ---------------- launch ----------------
extern "C" void kernel_launch(void* const* d_in, const int* in_sizes, int n_in,
                              void* d_out, int out_size) {
    const float* x   = (const float*)d_in[0];
    const float* W1  = (const float*)d_in[1];
    const float* b1  = (const float*)d_in[2];
    const float* Wg1 = (const float*)d_in[3];
    const float* Wg2 = (const float*)d_in[4];
    const float* W2  = (const float*)d_in[5];
    const float* b2  = (const float*)d_in[6];
    float* out = (float*)d_out;

    float *y_p;
    __nv_bfloat16 *xh, *xl, *oh, *ol, *w1h, *w1l, *w2h, *w2l;
    cudaGetSymbolAddress((void**)&y_p, g_y);
    cudaGetSymbolAddress((void**)&xh, g_xh);
    cudaGetSymbolAddress((void**)&xl, g_xl);
    cudaGetSymbolAddress((void**)&oh, g_oh);
    cudaGetSymbolAddress((void**)&ol, g_ol);
    cudaGetSymbolAddress((void**)&w1h, g_w1h);
    cudaGetSymbolAddress((void**)&w1l, g_w1l);
    cudaGetSymbolAddress((void**)&w2h, g_w2h);
    cudaGetSymbolAddress((void**)&w2l, g_w2l);

    cudaFuncSetAttribute(gemm_bf16split,
                         cudaFuncAttributeMaxDynamicSharedMemorySize, GEMM_SMEM);

    split_pair_kernel<<<(NROW * CIN / 4 + 255) / 256, 256>>>(x, xh, xl, NROW * CIN / 4);
    wsplit_kernel<<<dim3(D1 / 32, CIN / 32), dim3(32, 8)>>>(W1, w1h, w1l, CIN, D1);
    wsplit_kernel<<<dim3(NF / 32, NF / 32), dim3(32, 8)>>>(W2, w2h, w2l, NF, NF);

    gemm_bf16split<<<dim3(D1 / BN, NROW / BM), 256, GEMM_SMEM>>>(
        xh, xl, w1h, w1l, b1, y_p, NROW, D1, CIN);

    zero_a_kernel<<<(Bn * NF + 255) / 256, 256>>>();
    reduce_a_kernel<<<dim3(HW / 64, Bn), NF>>>();
    gating_kernel<<<Bn, 768>>>(Wg1, Wg2);
    combine_kernel<<<dim3(HW / 64, Bn), NF>>>();

    gemm_bf16split<<<dim3(NF / BN, NROW / BM), 256, GEMM_SMEM>>>(
        oh, ol, w2h, w2l, b2, out, NROW, NF, NF);
}

// round 5
// speedup vs baseline: 1.0362x; 1.0362x over previous
#include <cuda_runtime.h>
#include <cuda_bf16.h>
#include <cstdint>
#include <math.h>

// ---------------- problem constants ----------------
#define Bn   16
#define Hh   56
#define Ww   56
#define HW   (Hh*Ww)          // 3136
#define NROW (Bn*HW)          // 50176
#define CIN  384
#define NF   384
#define KK   3
#define D1   (NF*KK)          // 1152

// ---------------- device scratch ----------------
__device__ float          g_y[(size_t)NROW * D1];
__device__ __nv_bfloat16  g_xh[(size_t)NROW * CIN];
__device__ __nv_bfloat16  g_xl[(size_t)NROW * CIN];
__device__ __nv_bfloat16  g_oh[(size_t)NROW * NF];
__device__ __nv_bfloat16  g_ol[(size_t)NROW * NF];
__device__ __nv_bfloat16  g_w1h[(size_t)D1 * CIN];
__device__ __nv_bfloat16  g_w1l[(size_t)D1 * CIN];
__device__ __nv_bfloat16  g_w2h[(size_t)NF * NF];
__device__ __nv_bfloat16  g_w2l[(size_t)NF * NF];
__device__ float g_a[Bn * NF];
__device__ float g_abar[Bn * D1];

// ---------------- helpers ----------------
__device__ __forceinline__ uint32_t smem_u32(const void* p) {
    uint32_t a;
    asm("{ .reg .u64 t; cvta.to.shared.u64 t, %1; cvt.u32.u64 %0, t; }" : "=r"(a) : "l"(p));
    return a;
}
__device__ __forceinline__ void cp16(uint32_t s, const void* g) {
    asm volatile("cp.async.cg.shared.global [%0], [%1], 16;" :: "r"(s), "l"(g));
}
__device__ __forceinline__ void ldsm_x4(uint32_t& r0, uint32_t& r1, uint32_t& r2,
                                        uint32_t& r3, uint32_t addr) {
    asm volatile("ldmatrix.sync.aligned.m8n8.x4.shared.b16 {%0,%1,%2,%3}, [%4];"
                 : "=r"(r0), "=r"(r1), "=r"(r2), "=r"(r3) : "r"(addr));
}
__device__ __forceinline__ void mma_bf16(float* d, const uint32_t* a,
                                         uint32_t b0, uint32_t b1) {
    asm volatile("mma.sync.aligned.m16n8k16.row.col.f32.bf16.bf16.f32 "
        "{%0,%1,%2,%3}, {%4,%5,%6,%7}, {%8,%9}, {%0,%1,%2,%3};"
        : "+f"(d[0]), "+f"(d[1]), "+f"(d[2]), "+f"(d[3])
        : "r"(a[0]), "r"(a[1]), "r"(a[2]), "r"(a[3]), "r"(b0), "r"(b1));
}

// ---------------- bf16-split HMMA GEMM ----------------
// C[M,N] = (Ah+Al)[M,K] @ (Bh+Bl)[N,K]^T + bias; drop Al*Bl.
// CTA tile 128x128x32; 4 warps (2x2), warp tile 64x64 -> halves smem reads/MMA.
#define BM 128
#define BN 128
#define BK 32
#define PITCH 80
#define T_BYTES (128 * PITCH)
#define OFF_AH 0
#define OFF_AL (T_BYTES)
#define OFF_BH (2 * T_BYTES)
#define OFF_BL (3 * T_BYTES)
#define STAGE_BYTES (4 * T_BYTES)  // 40960
#define GEMM_SMEM (2 * STAGE_BYTES)

__device__ __forceinline__ void load_stage(
    uint32_t stg, const __nv_bfloat16* Ah, const __nv_bfloat16* Al,
    const __nv_bfloat16* Bh, const __nv_bfloat16* Bl,
    int bm0, int bn0, int k0, int K, int tid)
{
    #pragma unroll
    for (int t = 0; t < 4; ++t) {              // 512 chunks per array, 128 threads
        int idx = tid + t * 128;
        int r = idx >> 2, c = idx & 3;
        uint32_t so = r * PITCH + c * 16;
        size_t ga = (size_t)(bm0 + r) * K + k0 + c * 8;
        cp16(stg + OFF_AH + so, Ah + ga);
        cp16(stg + OFF_AL + so, Al + ga);
        size_t gb = (size_t)(bn0 + r) * K + k0 + c * 8;
        cp16(stg + OFF_BH + so, Bh + gb);
        cp16(stg + OFF_BL + so, Bl + gb);
    }
}

__global__ __launch_bounds__(128, 2)
void gemm_bf16split(const __nv_bfloat16* __restrict__ Ah,
                    const __nv_bfloat16* __restrict__ Al,
                    const __nv_bfloat16* __restrict__ Bh,
                    const __nv_bfloat16* __restrict__ Bl,
                    const float* __restrict__ bias,
                    float* __restrict__ C, int M, int N, int K)
{
    extern __shared__ char smem[];
    const uint32_t sbase = smem_u32(smem);
    const int tid = threadIdx.x, wid = tid >> 5, lane = tid & 31;
    const int warp_m = wid >> 1, warp_n = wid & 1;      // 2 x 2
    const int bn0 = blockIdx.x * BN, bm0 = blockIdx.y * BM;
    const int NC = K / BK;

    float acc[4][8][4] = {};

    const int a_r = (lane & 15);
    const int a_kb = ((lane >> 4) << 3) * 2;
    const int b_r = ((lane >> 4) << 3) + (lane & 7);
    const int b_kb = (((lane >> 3) & 1) << 3) * 2;

    load_stage(sbase, Ah, Al, Bh, Bl, bm0, bn0, 0, K, tid);
    asm volatile("cp.async.commit_group;" ::: "memory");

    for (int c = 0; c < NC; ++c) {
        if (c + 1 < NC) {
            load_stage(sbase + ((c + 1) & 1) * STAGE_BYTES,
                       Ah, Al, Bh, Bl, bm0, bn0, (c + 1) * BK, K, tid);
            asm volatile("cp.async.commit_group;" ::: "memory");
            asm volatile("cp.async.wait_group 1;" ::: "memory");
        } else {
            asm volatile("cp.async.wait_group 0;" ::: "memory");
        }
        __syncthreads();

        const uint32_t stg = sbase + (c & 1) * STAGE_BYTES;
        #pragma unroll
        for (int ks = 0; ks < 2; ++ks) {
            const int koff = ks * 32;
            uint32_t ah[4][4], al[4][4], bh[4][4], bl[4][4];
            #pragma unroll
            for (int i = 0; i < 4; ++i) {
                uint32_t ra = (warp_m * 64 + i * 16 + a_r) * PITCH + koff + a_kb;
                ldsm_x4(ah[i][0], ah[i][1], ah[i][2], ah[i][3], stg + OFF_AH + ra);
                ldsm_x4(al[i][0], al[i][1], al[i][2], al[i][3], stg + OFF_AL + ra);
            }
            #pragma unroll
            for (int jp = 0; jp < 4; ++jp) {
                uint32_t rb = (warp_n * 64 + jp * 16 + b_r) * PITCH + koff + b_kb;
                ldsm_x4(bh[jp][0], bh[jp][1], bh[jp][2], bh[jp][3], stg + OFF_BH + rb);
                ldsm_x4(bl[jp][0], bl[jp][1], bl[jp][2], bl[jp][3], stg + OFF_BL + rb);
            }
            #pragma unroll
            for (int i = 0; i < 4; ++i)
                #pragma unroll
                for (int j = 0; j < 8; ++j) {
                    const int jp = j >> 1, jj = j & 1;
                    mma_bf16(acc[i][j], ah[i], bh[jp][jj * 2], bh[jp][jj * 2 + 1]);
                    mma_bf16(acc[i][j], ah[i], bl[jp][jj * 2], bl[jp][jj * 2 + 1]);
                    mma_bf16(acc[i][j], al[i], bh[jp][jj * 2], bh[jp][jj * 2 + 1]);
                }
        }
        __syncthreads();
    }

    #pragma unroll
    for (int i = 0; i < 4; ++i) {
        int row0 = bm0 + warp_m * 64 + i * 16 + (lane >> 2);
        #pragma unroll
        for (int j = 0; j < 8; ++j) {
            int col = bn0 + warp_n * 64 + j * 8 + (lane & 3) * 2;
            float b0 = bias[col], b1 = bias[col + 1];
            float2 v0 = {acc[i][j][0] + b0, acc[i][j][1] + b1};
            float2 v1 = {acc[i][j][2] + b0, acc[i][j][3] + b1};
            *reinterpret_cast<float2*>(C + (size_t)row0 * N + col) = v0;
            *reinterpret_cast<float2*>(C + (size_t)(row0 + 8) * N + col) = v1;
        }
    }
}

// ---------------- conversion kernels ----------------
__device__ __forceinline__ void split1(float v, __nv_bfloat16& h, __nv_bfloat16& l) {
    h = __float2bfloat16_rn(v);
    l = __float2bfloat16_rn(v - __bfloat162float(h));
}

__global__ __launch_bounds__(256)
void split_pair_kernel(const float* __restrict__ src,
                       __nv_bfloat16* __restrict__ h, __nv_bfloat16* __restrict__ l, int n4) {
    int i = blockIdx.x * blockDim.x + threadIdx.x;
    if (i >= n4) return;
    float4 v = reinterpret_cast<const float4*>(src)[i];
    __nv_bfloat16 h0, h1, h2, h3, l0, l1, l2, l3;
    split1(v.x, h0, l0); split1(v.y, h1, l1); split1(v.z, h2, l2); split1(v.w, h3, l3);
    __nv_bfloat162* hp = reinterpret_cast<__nv_bfloat162*>(h);
    __nv_bfloat162* lp = reinterpret_cast<__nv_bfloat162*>(l);
    hp[2 * i]     = __nv_bfloat162{h0, h1};
    hp[2 * i + 1] = __nv_bfloat162{h2, h3};
    lp[2 * i]     = __nv_bfloat162{l0, l1};
    lp[2 * i + 1] = __nv_bfloat162{l2, l3};
}

__global__ void wsplit_kernel(const float* __restrict__ W,
                              __nv_bfloat16* __restrict__ Oh, __nv_bfloat16* __restrict__ Ol,
                              int K, int N) {
    __shared__ float t[32][33];
    int n0 = blockIdx.x * 32, k0 = blockIdx.y * 32;
    int tx = threadIdx.x, ty = threadIdx.y;
    #pragma unroll
    for (int r = 0; r < 4; r++)
        t[ty + 8 * r][tx] = W[(size_t)(k0 + ty + 8 * r) * N + n0 + tx];
    __syncthreads();
    #pragma unroll
    for (int r = 0; r < 4; r++) {
        int n = n0 + ty + 8 * r, k = k0 + tx;
        float v = t[tx][ty + 8 * r];
        __nv_bfloat16 h, l; split1(v, h, l);
        Oh[(size_t)n * K + k] = h;
        Ol[(size_t)n * K + k] = l;
    }
}

// ---------------- shift / gating path ----------------
__device__ __forceinline__ int shift_src(int mode, int q, int h, int w) {
    int hh = h, ww = w;
    if (mode == 1) {
        if      (q == 0) ww = max(w - 1, 0);
        else if (q == 1) ww = min(w + 1, Ww - 1);
        else if (q == 2) hh = max(h - 1, 0);
        else             hh = min(h + 1, Hh - 1);
    } else {
        if      (q == 0) hh = max(h - 1, 0);
        else if (q == 1) hh = min(h + 1, Hh - 1);
        else if (q == 2) ww = max(w - 1, 0);
        else             ww = min(w + 1, Ww - 1);
    }
    return hh * Ww + ww;
}

__global__ void zero_a_kernel() {
    int i = blockIdx.x * blockDim.x + threadIdx.x;
    if (i < Bn * NF) g_a[i] = 0.0f;
}

__global__ __launch_bounds__(384)
void reduce_a_kernel() {
    const int b = blockIdx.y, chunk = blockIdx.x, c = threadIdx.x;
    const int q = c / (NF / 4);
    const float* yb = g_y + (size_t)b * HW * D1;
    float acc = 0.0f;
    for (int j = 0; j < 64; j++) {
        int hw = chunk * 64 + j;
        int h = hw / Ww, w = hw % Ww;
        int s1 = shift_src(1, q, h, w);
        int s2 = shift_src(2, q, h, w);
        acc += yb[(size_t)s1 * D1 + c]
             + yb[(size_t)s2 * D1 + NF + c]
             + yb[(size_t)hw * D1 + 2 * NF + c];
    }
    atomicAdd(&g_a[b * NF + c], acc);
}

__device__ __forceinline__ float gelu_t(float x) {
    float t = tanhf(0.7978845608028654f * (x + 0.044715f * x * x * x));
    return 0.5f * x * (1.0f + t);
}

__global__ __launch_bounds__(768)
void gating_kernel(const float* __restrict__ Wg1, const float* __restrict__ Wg2) {
    __shared__ float a_s[NF];
    __shared__ float h_s[NF];
    __shared__ float part[2][NF];
    const int b = blockIdx.x;
    const int tid = threadIdx.x;
    const int half = tid / NF;
    const int cc = tid - half * NF;
    if (tid < NF) a_s[tid] = g_a[b * NF + tid];
    __syncthreads();

    {
        float s = 0.0f;
        const int i0 = half * (NF / 2);
        #pragma unroll 16
        for (int j = 0; j < NF / 2; j++)
            s += a_s[i0 + j] * Wg1[(size_t)(i0 + j) * NF + cc];
        part[half][cc] = s;
    }
    __syncthreads();
    if (tid < NF) h_s[tid] = gelu_t(part[0][tid] + part[1][tid]);
    __syncthreads();

    float s0 = 0.0f, s1 = 0.0f, s2 = 0.0f;
    {
        const int i0 = half * (NF / 2);
        #pragma unroll 8
        for (int j = 0; j < NF / 2; j++) {
            float hv = h_s[i0 + j];
            const float* w = Wg2 + (size_t)(i0 + j) * D1 + cc;
            s0 += hv * w[0];
            s1 += hv * w[NF];
            s2 += hv * w[2 * NF];
        }
    }
    part[half][cc] = s0; __syncthreads();
    float a0 = (tid < NF) ? part[0][tid] + part[1][tid] : 0.0f; __syncthreads();
    part[half][cc] = s1; __syncthreads();
    float a1 = (tid < NF) ? part[0][tid] + part[1][tid] : 0.0f; __syncthreads();
    part[half][cc] = s2; __syncthreads();
    float a2 = (tid < NF) ? part[0][tid] + part[1][tid] : 0.0f;

    if (tid < NF) {
        float m = fmaxf(a0, fmaxf(a1, a2));
        float e0 = expf(a0 - m), e1 = expf(a1 - m), e2 = expf(a2 - m);
        float inv = 1.0f / (e0 + e1 + e2);
        g_abar[b * D1 + tid] = e0 * inv;
        g_abar[b * D1 + NF + tid] = e1 * inv;
        g_abar[b * D1 + 2 * NF + tid] = e2 * inv;
    }
}

__global__ __launch_bounds__(384)
void combine_kernel() {
    __shared__ float ab[D1];
    const int b = blockIdx.y, chunk = blockIdx.x, c = threadIdx.x;
    for (int i = c; i < D1; i += NF) ab[i] = g_abar[b * D1 + i];
    __syncthreads();

    const int q = c / (NF / 4);
    const float a0 = ab[c], a1 = ab[NF + c], a2 = ab[2 * NF + c];
    const float* yb = g_y + (size_t)b * HW * D1;
    __nv_bfloat16* oh = g_oh + (size_t)b * HW * NF;
    __nv_bfloat16* ol = g_ol + (size_t)b * HW * NF;

    for (int j = 0; j < 64; j++) {
        int hw = chunk * 64 + j;
        int h = hw / Ww, w = hw % Ww;
        int s1 = shift_src(1, q, h, w);
        int s2 = shift_src(2, q, h, w);
        float v = a0 * yb[(size_t)s1 * D1 + c]
                + a1 * yb[(size_t)s2 * D1 + NF + c]
                + a2 * yb[(size_t)hw * D1 + 2 * NF + c];
        __nv_bfloat16 hv, lv; split1(v, hv, lv);
        oh[(size_t)hw * NF + c] = hv;
        ol[(size_t)hw * NF + c] = lv;
    }
}

// ---------------- launch ----------------
extern "C" void kernel_launch(void* const* d_in, const int* in_sizes, int n_in,
                              void* d_out, int out_size) {
    const float* x   = (const float*)d_in[0];
    const float* W1  = (const float*)d_in[1];
    const float* b1  = (const float*)d_in[2];
    const float* Wg1 = (const float*)d_in[3];
    const float* Wg2 = (const float*)d_in[4];
    const float* W2  = (const float*)d_in[5];
    const float* b2  = (const float*)d_in[6];
    float* out = (float*)d_out;

    float *y_p;
    __nv_bfloat16 *xh, *xl, *oh, *ol, *w1h, *w1l, *w2h, *w2l;
    cudaGetSymbolAddress((void**)&y_p, g_y);
    cudaGetSymbolAddress((void**)&xh, g_xh);
    cudaGetSymbolAddress((void**)&xl, g_xl);
    cudaGetSymbolAddress((void**)&oh, g_oh);
    cudaGetSymbolAddress((void**)&ol, g_ol);
    cudaGetSymbolAddress((void**)&w1h, g_w1h);
    cudaGetSymbolAddress((void**)&w1l, g_w1l);
    cudaGetSymbolAddress((void**)&w2h, g_w2h);
    cudaGetSymbolAddress((void**)&w2l, g_w2l);

    cudaFuncSetAttribute(gemm_bf16split,
                         cudaFuncAttributeMaxDynamicSharedMemorySize, GEMM_SMEM);

    split_pair_kernel<<<(NROW * CIN / 4 + 255) / 256, 256>>>(x, xh, xl, NROW * CIN / 4);
    wsplit_kernel<<<dim3(D1 / 32, CIN / 32), dim3(32, 8)>>>(W1, w1h, w1l, CIN, D1);
    wsplit_kernel<<<dim3(NF / 32, NF / 32), dim3(32, 8)>>>(W2, w2h, w2l, NF, NF);

    gemm_bf16split<<<dim3(D1 / BN, NROW / BM), 128, GEMM_SMEM>>>(
        xh, xl, w1h, w1l, b1, y_p, NROW, D1, CIN);

    zero_a_kernel<<<(Bn * NF + 255) / 256, 256>>>();
    reduce_a_kernel<<<dim3(HW / 64, Bn), NF>>>();
    gating_kernel<<<Bn, 768>>>(Wg1, Wg2);
    combine_kernel<<<dim3(HW / 64, Bn), NF>>>();

    gemm_bf16split<<<dim3(NF / BN, NROW / BM), 128, GEMM_SMEM>>>(
        oh, ol, w2h, w2l, b2, out, NROW, NF, NF);
}

// round 8
// speedup vs baseline: 1.0679x; 1.0306x over previous
#include <cuda_runtime.h>
#include <cuda_fp16.h>
#include <cstdint>
#include <math.h>

// ---------------- problem constants ----------------
#define Bn   16
#define Hh   56
#define Ww   56
#define HW   (Hh*Ww)          // 3136
#define NROW (Bn*HW)          // 50176
#define CIN  384
#define NF   384
#define KK   3
#define D1   (NF*KK)          // 1152

// ---------------- device scratch ----------------
__device__ __half  g_yh[(size_t)NROW * D1];     // y hi (fp16 pair replaces fp32 y)
__device__ __half  g_yl[(size_t)NROW * D1];     // y lo
__device__ __half  g_xh[(size_t)NROW * CIN];    // x hi
__device__ __half  g_xl[(size_t)NROW * CIN];    // x lo
__device__ __half  g_oc[(size_t)NROW * NF];     // combined (single fp16)
__device__ __half  g_w1h[(size_t)D1 * CIN];     // W1^T hi  [N,K]
__device__ __half  g_w1l[(size_t)D1 * CIN];
__device__ __half  g_w2h[(size_t)NF * NF];      // W2^T hi
__device__ __half  g_w2l[(size_t)NF * NF];
__device__ float g_a[Bn * NF];
__device__ float g_abar[Bn * D1];

// ---------------- helpers ----------------
__device__ __forceinline__ uint32_t smem_u32(const void* p) {
    uint32_t a;
    asm("{ .reg .u64 t; cvta.to.shared.u64 t, %1; cvt.u32.u64 %0, t; }" : "=r"(a) : "l"(p));
    return a;
}
__device__ __forceinline__ void cp16(uint32_t s, const void* g) {
    asm volatile("cp.async.cg.shared.global [%0], [%1], 16;" :: "r"(s), "l"(g));
}
__device__ __forceinline__ void ldsm_x4(uint32_t& r0, uint32_t& r1, uint32_t& r2,
                                        uint32_t& r3, uint32_t addr) {
    asm volatile("ldmatrix.sync.aligned.m8n8.x4.shared.b16 {%0,%1,%2,%3}, [%4];"
                 : "=r"(r0), "=r"(r1), "=r"(r2), "=r"(r3) : "r"(addr));
}
__device__ __forceinline__ void mma_f16(float* d, const uint32_t* a,
                                        uint32_t b0, uint32_t b1) {
    asm volatile("mma.sync.aligned.m16n8k16.row.col.f32.f16.f16.f32 "
        "{%0,%1,%2,%3}, {%4,%5,%6,%7}, {%8,%9}, {%0,%1,%2,%3};"
        : "+f"(d[0]), "+f"(d[1]), "+f"(d[2]), "+f"(d[3])
        : "r"(a[0]), "r"(a[1]), "r"(a[2]), "r"(a[3]), "r"(b0), "r"(b1));
}

#define BM 128
#define BN 128
#define BK 32
#define PITCH 80
#define T_BYTES (128 * PITCH)          // 10240

// ==================== GEMM1: fp16 3-product, fp16-pair output ====================
// y = (Ah+Al) @ (Bh+Bl)^T + bias, drop Al*Bl. Output written as (yh, yl) fp16.
#define G1_OFF_AH 0
#define G1_OFF_AL (T_BYTES)
#define G1_OFF_BH (2 * T_BYTES)
#define G1_OFF_BL (3 * T_BYTES)
#define G1_STAGE (4 * T_BYTES)         // 40960
#define G1_SMEM (2 * G1_STAGE)         // 81920

__device__ __forceinline__ void g1_load_stage(
    uint32_t stg, const __half* Ah, const __half* Al,
    const __half* Bh, const __half* Bl,
    int bm0, int bn0, int k0, int K, int tid)
{
    #pragma unroll
    for (int t = 0; t < 4; ++t) {
        int idx = tid + t * 128;
        int r = idx >> 2, c = idx & 3;
        uint32_t so = r * PITCH + c * 16;
        size_t ga = (size_t)(bm0 + r) * K + k0 + c * 8;
        cp16(stg + G1_OFF_AH + so, Ah + ga);
        cp16(stg + G1_OFF_AL + so, Al + ga);
        size_t gb = (size_t)(bn0 + r) * K + k0 + c * 8;
        cp16(stg + G1_OFF_BH + so, Bh + gb);
        cp16(stg + G1_OFF_BL + so, Bl + gb);
    }
}

__global__ __launch_bounds__(128, 2)
void gemm1_f16x3(const __half* __restrict__ Ah,
                 const __half* __restrict__ Al,
                 const __half* __restrict__ Bh,
                 const __half* __restrict__ Bl,
                 const float* __restrict__ bias,
                 __half* __restrict__ Ch, __half* __restrict__ Cl,
                 int M, int N, int K)
{
    extern __shared__ char smem[];
    const uint32_t sbase = smem_u32(smem);
    const int tid = threadIdx.x, wid = tid >> 5, lane = tid & 31;
    const int warp_m = wid >> 1, warp_n = wid & 1;
    const int bn0 = blockIdx.x * BN, bm0 = blockIdx.y * BM;
    const int NC = K / BK;

    float acc[4][8][4] = {};

    const int a_r = (lane & 15);
    const int a_kb = ((lane >> 4) << 3) * 2;
    const int b_r = ((lane >> 4) << 3) + (lane & 7);
    const int b_kb = (((lane >> 3) & 1) << 3) * 2;

    g1_load_stage(sbase, Ah, Al, Bh, Bl, bm0, bn0, 0, K, tid);
    asm volatile("cp.async.commit_group;" ::: "memory");

    for (int c = 0; c < NC; ++c) {
        if (c + 1 < NC) {
            g1_load_stage(sbase + ((c + 1) & 1) * G1_STAGE,
                          Ah, Al, Bh, Bl, bm0, bn0, (c + 1) * BK, K, tid);
            asm volatile("cp.async.commit_group;" ::: "memory");
            asm volatile("cp.async.wait_group 1;" ::: "memory");
        } else {
            asm volatile("cp.async.wait_group 0;" ::: "memory");
        }
        __syncthreads();

        const uint32_t stg = sbase + (c & 1) * G1_STAGE;
        #pragma unroll
        for (int ks = 0; ks < 2; ++ks) {
            const int koff = ks * 32;
            uint32_t ah[4][4], al[4][4], bh[4][4], bl[4][4];
            #pragma unroll
            for (int i = 0; i < 4; ++i) {
                uint32_t ra = (warp_m * 64 + i * 16 + a_r) * PITCH + koff + a_kb;
                ldsm_x4(ah[i][0], ah[i][1], ah[i][2], ah[i][3], stg + G1_OFF_AH + ra);
                ldsm_x4(al[i][0], al[i][1], al[i][2], al[i][3], stg + G1_OFF_AL + ra);
            }
            #pragma unroll
            for (int jp = 0; jp < 4; ++jp) {
                uint32_t rb = (warp_n * 64 + jp * 16 + b_r) * PITCH + koff + b_kb;
                ldsm_x4(bh[jp][0], bh[jp][1], bh[jp][2], bh[jp][3], stg + G1_OFF_BH + rb);
                ldsm_x4(bl[jp][0], bl[jp][1], bl[jp][2], bl[jp][3], stg + G1_OFF_BL + rb);
            }
            #pragma unroll
            for (int i = 0; i < 4; ++i)
                #pragma unroll
                for (int j = 0; j < 8; ++j) {
                    const int jp = j >> 1, jj = j & 1;
                    mma_f16(acc[i][j], ah[i], bh[jp][jj * 2], bh[jp][jj * 2 + 1]);
                    mma_f16(acc[i][j], ah[i], bl[jp][jj * 2], bl[jp][jj * 2 + 1]);
                    mma_f16(acc[i][j], al[i], bh[jp][jj * 2], bh[jp][jj * 2 + 1]);
                }
        }
        __syncthreads();
    }

    // epilogue: bias, then split each value into fp16 hi/lo and store pairs
    #pragma unroll
    for (int i = 0; i < 4; ++i) {
        int row0 = bm0 + warp_m * 64 + i * 16 + (lane >> 2);
        #pragma unroll
        for (int j = 0; j < 8; ++j) {
            int col = bn0 + warp_n * 64 + j * 8 + (lane & 3) * 2;
            float b0 = bias[col], b1 = bias[col + 1];
            float v00 = acc[i][j][0] + b0, v01 = acc[i][j][1] + b1;
            float v10 = acc[i][j][2] + b0, v11 = acc[i][j][3] + b1;
            __half h00 = __float2half_rn(v00), h01 = __float2half_rn(v01);
            __half h10 = __float2half_rn(v10), h11 = __float2half_rn(v11);
            __half l00 = __float2half_rn(v00 - __half2float(h00));
            __half l01 = __float2half_rn(v01 - __half2float(h01));
            __half l10 = __float2half_rn(v10 - __half2float(h10));
            __half l11 = __float2half_rn(v11 - __half2float(h11));
            *reinterpret_cast<__half2*>(Ch + (size_t)row0 * N + col)       = __half2{h00, h01};
            *reinterpret_cast<__half2*>(Ch + (size_t)(row0 + 8) * N + col) = __half2{h10, h11};
            *reinterpret_cast<__half2*>(Cl + (size_t)row0 * N + col)       = __half2{l00, l01};
            *reinterpret_cast<__half2*>(Cl + (size_t)(row0 + 8) * N + col) = __half2{l10, l11};
        }
    }
}

// ==================== GEMM2: fp16 2-product, fp32 output ====================
// out = A @ (Bh+Bl)^T + bias.  3-stage pipeline.
#define G2_OFF_A  0
#define G2_OFF_BH (T_BYTES)
#define G2_OFF_BL (2 * T_BYTES)
#define G2_STAGE (3 * T_BYTES)         // 30720
#define G2_NSTAGE 3
#define G2_SMEM (G2_NSTAGE * G2_STAGE) // 92160

__device__ __forceinline__ void g2_load_stage(
    uint32_t stg, const __half* A, const __half* Bh, const __half* Bl,
    int bm0, int bn0, int k0, int K, int tid)
{
    #pragma unroll
    for (int t = 0; t < 4; ++t) {
        int idx = tid + t * 128;
        int r = idx >> 2, c = idx & 3;
        uint32_t so = r * PITCH + c * 16;
        size_t ga = (size_t)(bm0 + r) * K + k0 + c * 8;
        cp16(stg + G2_OFF_A + so, A + ga);
        size_t gb = (size_t)(bn0 + r) * K + k0 + c * 8;
        cp16(stg + G2_OFF_BH + so, Bh + gb);
        cp16(stg + G2_OFF_BL + so, Bl + gb);
    }
}

__global__ __launch_bounds__(128, 2)
void gemm2_f16x2(const __half* __restrict__ A,
                 const __half* __restrict__ Bh,
                 const __half* __restrict__ Bl,
                 const float* __restrict__ bias,
                 float* __restrict__ C, int M, int N, int K)
{
    extern __shared__ char smem[];
    const uint32_t sbase = smem_u32(smem);
    const int tid = threadIdx.x, wid = tid >> 5, lane = tid & 31;
    const int warp_m = wid >> 1, warp_n = wid & 1;
    const int bn0 = blockIdx.x * BN, bm0 = blockIdx.y * BM;
    const int NC = K / BK;

    float acc[4][8][4] = {};

    const int a_r = (lane & 15);
    const int a_kb = ((lane >> 4) << 3) * 2;
    const int b_r = ((lane >> 4) << 3) + (lane & 7);
    const int b_kb = (((lane >> 3) & 1) << 3) * 2;

    g2_load_stage(sbase + 0 * G2_STAGE, A, Bh, Bl, bm0, bn0, 0, K, tid);
    asm volatile("cp.async.commit_group;" ::: "memory");
    g2_load_stage(sbase + 1 * G2_STAGE, A, Bh, Bl, bm0, bn0, BK, K, tid);
    asm volatile("cp.async.commit_group;" ::: "memory");

    int buf = 0;
    for (int c = 0; c < NC; ++c) {
        if (c + 1 < NC) {
            asm volatile("cp.async.wait_group 1;" ::: "memory");
        } else {
            asm volatile("cp.async.wait_group 0;" ::: "memory");
        }
        __syncthreads();
        if (c + 2 < NC) {
            int nb = buf + 2; if (nb >= G2_NSTAGE) nb -= G2_NSTAGE;
            g2_load_stage(sbase + nb * G2_STAGE, A, Bh, Bl, bm0, bn0, (c + 2) * BK, K, tid);
            asm volatile("cp.async.commit_group;" ::: "memory");
        }

        const uint32_t stg = sbase + buf * G2_STAGE;
        #pragma unroll
        for (int ks = 0; ks < 2; ++ks) {
            const int koff = ks * 32;
            uint32_t a[4][4], bh[4][4], bl[4][4];
            #pragma unroll
            for (int i = 0; i < 4; ++i) {
                uint32_t ra = (warp_m * 64 + i * 16 + a_r) * PITCH + koff + a_kb;
                ldsm_x4(a[i][0], a[i][1], a[i][2], a[i][3], stg + G2_OFF_A + ra);
            }
            #pragma unroll
            for (int jp = 0; jp < 4; ++jp) {
                uint32_t rb = (warp_n * 64 + jp * 16 + b_r) * PITCH + koff + b_kb;
                ldsm_x4(bh[jp][0], bh[jp][1], bh[jp][2], bh[jp][3], stg + G2_OFF_BH + rb);
                ldsm_x4(bl[jp][0], bl[jp][1], bl[jp][2], bl[jp][3], stg + G2_OFF_BL + rb);
            }
            #pragma unroll
            for (int i = 0; i < 4; ++i)
                #pragma unroll
                for (int j = 0; j < 8; ++j) {
                    const int jp = j >> 1, jj = j & 1;
                    mma_f16(acc[i][j], a[i], bh[jp][jj * 2], bh[jp][jj * 2 + 1]);
                    mma_f16(acc[i][j], a[i], bl[jp][jj * 2], bl[jp][jj * 2 + 1]);
                }
        }
        __syncthreads();
        if (++buf == G2_NSTAGE) buf = 0;
    }

    #pragma unroll
    for (int i = 0; i < 4; ++i) {
        int row0 = bm0 + warp_m * 64 + i * 16 + (lane >> 2);
        #pragma unroll
        for (int j = 0; j < 8; ++j) {
            int col = bn0 + warp_n * 64 + j * 8 + (lane & 3) * 2;
            float b0 = bias[col], b1 = bias[col + 1];
            float2 v0 = {acc[i][j][0] + b0, acc[i][j][1] + b1};
            float2 v1 = {acc[i][j][2] + b0, acc[i][j][3] + b1};
            *reinterpret_cast<float2*>(C + (size_t)row0 * N + col) = v0;
            *reinterpret_cast<float2*>(C + (size_t)(row0 + 8) * N + col) = v1;
        }
    }
}

// ---------------- conversion kernels ----------------
__global__ __launch_bounds__(256)
void splitx_kernel(const float* __restrict__ src,
                   __half* __restrict__ h, __half* __restrict__ l, int n4) {
    int i = blockIdx.x * blockDim.x + threadIdx.x;
    if (i >= n4) return;
    float4 v = reinterpret_cast<const float4*>(src)[i];
    __half h0 = __float2half_rn(v.x), h1 = __float2half_rn(v.y);
    __half h2 = __float2half_rn(v.z), h3 = __float2half_rn(v.w);
    __half l0 = __float2half_rn(v.x - __half2float(h0));
    __half l1 = __float2half_rn(v.y - __half2float(h1));
    __half l2 = __float2half_rn(v.z - __half2float(h2));
    __half l3 = __float2half_rn(v.w - __half2float(h3));
    __half2* hp = reinterpret_cast<__half2*>(h);
    __half2* lp = reinterpret_cast<__half2*>(l);
    hp[2 * i]     = __half2{h0, h1};
    hp[2 * i + 1] = __half2{h2, h3};
    lp[2 * i]     = __half2{l0, l1};
    lp[2 * i + 1] = __half2{l2, l3};
}

// W [K,N] row-major -> Oh/Ol [N,K] fp16 hi/lo (transpose + split)
__global__ void wsplit_kernel(const float* __restrict__ W,
                              __half* __restrict__ Oh, __half* __restrict__ Ol,
                              int K, int N) {
    __shared__ float t[32][33];
    int n0 = blockIdx.x * 32, k0 = blockIdx.y * 32;
    int tx = threadIdx.x, ty = threadIdx.y;
    #pragma unroll
    for (int r = 0; r < 4; r++)
        t[ty + 8 * r][tx] = W[(size_t)(k0 + ty + 8 * r) * N + n0 + tx];
    __syncthreads();
    #pragma unroll
    for (int r = 0; r < 4; r++) {
        int n = n0 + ty + 8 * r, k = k0 + tx;
        float v = t[tx][ty + 8 * r];
        __half h = __float2half_rn(v);
        __half l = __float2half_rn(v - __half2float(h));
        Oh[(size_t)n * K + k] = h;
        Ol[(size_t)n * K + k] = l;
    }
}

// ---------------- shift / gating path ----------------
__device__ __forceinline__ int shift_src(int mode, int q, int h, int w) {
    int hh = h, ww = w;
    if (mode == 1) {
        if      (q == 0) ww = max(w - 1, 0);
        else if (q == 1) ww = min(w + 1, Ww - 1);
        else if (q == 2) hh = max(h - 1, 0);
        else             hh = min(h + 1, Hh - 1);
    } else {
        if      (q == 0) hh = max(h - 1, 0);
        else if (q == 1) hh = min(h + 1, Hh - 1);
        else if (q == 2) ww = max(w - 1, 0);
        else             ww = min(w + 1, Ww - 1);
    }
    return hh * Ww + ww;
}

__global__ void zero_a_kernel() {
    int i = blockIdx.x * blockDim.x + threadIdx.x;
    if (i < Bn * NF) g_a[i] = 0.0f;
}

// reads only y-hi (fp16) — gate statistics are robust to 2.4e-4 noise
__global__ __launch_bounds__(384)
void reduce_a_kernel() {
    const int b = blockIdx.y, chunk = blockIdx.x, c = threadIdx.x;
    const int q = c / (NF / 4);
    const __half* yb = g_yh + (size_t)b * HW * D1;
    float acc = 0.0f;
    for (int j = 0; j < 64; j++) {
        int hw = chunk * 64 + j;
        int h = hw / Ww, w = hw % Ww;
        int s1 = shift_src(1, q, h, w);
        int s2 = shift_src(2, q, h, w);
        acc += __half2float(yb[(size_t)s1 * D1 + c])
             + __half2float(yb[(size_t)s2 * D1 + NF + c])
             + __half2float(yb[(size_t)hw * D1 + 2 * NF + c]);
    }
    atomicAdd(&g_a[b * NF + c], acc);
}

__device__ __forceinline__ float gelu_t(float x) {
    float t = tanhf(0.7978845608028654f * (x + 0.044715f * x * x * x));
    return 0.5f * x * (1.0f + t);
}

__global__ __launch_bounds__(768)
void gating_kernel(const float* __restrict__ Wg1, const float* __restrict__ Wg2) {
    __shared__ float a_s[NF];
    __shared__ float h_s[NF];
    __shared__ float part[2][NF];
    const int b = blockIdx.x;
    const int tid = threadIdx.x;
    const int half = tid / NF;
    const int cc = tid - half * NF;
    if (tid < NF) a_s[tid] = g_a[b * NF + tid];
    __syncthreads();

    {
        float s = 0.0f;
        const int i0 = half * (NF / 2);
        #pragma unroll 16
        for (int j = 0; j < NF / 2; j++)
            s += a_s[i0 + j] * Wg1[(size_t)(i0 + j) * NF + cc];
        part[half][cc] = s;
    }
    __syncthreads();
    if (tid < NF) h_s[tid] = gelu_t(part[0][tid] + part[1][tid]);
    __syncthreads();

    float s0 = 0.0f, s1 = 0.0f, s2 = 0.0f;
    {
        const int i0 = half * (NF / 2);
        #pragma unroll 8
        for (int j = 0; j < NF / 2; j++) {
            float hv = h_s[i0 + j];
            const float* w = Wg2 + (size_t)(i0 + j) * D1 + cc;
            s0 += hv * w[0];
            s1 += hv * w[NF];
            s2 += hv * w[2 * NF];
        }
    }
    part[half][cc] = s0; __syncthreads();
    float a0 = (tid < NF) ? part[0][tid] + part[1][tid] : 0.0f; __syncthreads();
    part[half][cc] = s1; __syncthreads();
    float a1 = (tid < NF) ? part[0][tid] + part[1][tid] : 0.0f; __syncthreads();
    part[half][cc] = s2; __syncthreads();
    float a2 = (tid < NF) ? part[0][tid] + part[1][tid] : 0.0f;

    if (tid < NF) {
        float m = fmaxf(a0, fmaxf(a1, a2));
        float e0 = expf(a0 - m), e1 = expf(a1 - m), e2 = expf(a2 - m);
        float inv = 1.0f / (e0 + e1 + e2);
        g_abar[b * D1 + tid] = e0 * inv;
        g_abar[b * D1 + NF + tid] = e1 * inv;
        g_abar[b * D1 + 2 * NF + tid] = e2 * inv;
    }
}

// reads y hi+lo pair (fp32-accurate reconstruction), writes single fp16
__global__ __launch_bounds__(384)
void combine_kernel() {
    __shared__ float ab[D1];
    const int b = blockIdx.y, chunk = blockIdx.x, c = threadIdx.x;
    for (int i = c; i < D1; i += NF) ab[i] = g_abar[b * D1 + i];
    __syncthreads();

    const int q = c / (NF / 4);
    const float a0 = ab[c], a1 = ab[NF + c], a2 = ab[2 * NF + c];
    const __half* yh = g_yh + (size_t)b * HW * D1;
    const __half* yl = g_yl + (size_t)b * HW * D1;
    __half* oc = g_oc + (size_t)b * HW * NF;

    for (int j = 0; j < 64; j++) {
        int hw = chunk * 64 + j;
        int h = hw / Ww, w = hw % Ww;
        int s1 = shift_src(1, q, h, w);
        int s2 = shift_src(2, q, h, w);
        size_t i1 = (size_t)s1 * D1 + c;
        size_t i2 = (size_t)s2 * D1 + NF + c;
        size_t i3 = (size_t)hw * D1 + 2 * NF + c;
        float v = a0 * (__half2float(yh[i1]) + __half2float(yl[i1]))
                + a1 * (__half2float(yh[i2]) + __half2float(yl[i2]))
                + a2 * (__half2float(yh[i3]) + __half2float(yl[i3]));
        oc[(size_t)hw * NF + c] = __float2half_rn(v);
    }
}

// ---------------- launch ----------------
extern "C" void kernel_launch(void* const* d_in, const int* in_sizes, int n_in,
                              void* d_out, int out_size) {
    const float* x   = (const float*)d_in[0];
    const float* W1  = (const float*)d_in[1];
    const float* b1  = (const float*)d_in[2];
    const float* Wg1 = (const float*)d_in[3];
    const float* Wg2 = (const float*)d_in[4];
    const float* W2  = (const float*)d_in[5];
    const float* b2  = (const float*)d_in[6];
    float* out = (float*)d_out;

    __half *yh, *yl, *xh, *xl, *oc, *w1h, *w1l, *w2h, *w2l;
    cudaGetSymbolAddress((void**)&yh, g_yh);
    cudaGetSymbolAddress((void**)&yl, g_yl);
    cudaGetSymbolAddress((void**)&xh, g_xh);
    cudaGetSymbolAddress((void**)&xl, g_xl);
    cudaGetSymbolAddress((void**)&oc, g_oc);
    cudaGetSymbolAddress((void**)&w1h, g_w1h);
    cudaGetSymbolAddress((void**)&w1l, g_w1l);
    cudaGetSymbolAddress((void**)&w2h, g_w2h);
    cudaGetSymbolAddress((void**)&w2l, g_w2l);

    cudaFuncSetAttribute(gemm1_f16x3,
                         cudaFuncAttributeMaxDynamicSharedMemorySize, G1_SMEM);
    cudaFuncSetAttribute(gemm2_f16x2,
                         cudaFuncAttributeMaxDynamicSharedMemorySize, G2_SMEM);

    splitx_kernel<<<(NROW * CIN / 4 + 255) / 256, 256>>>(x, xh, xl, NROW * CIN / 4);
    wsplit_kernel<<<dim3(D1 / 32, CIN / 32), dim3(32, 8)>>>(W1, w1h, w1l, CIN, D1);
    wsplit_kernel<<<dim3(NF / 32, NF / 32), dim3(32, 8)>>>(W2, w2h, w2l, NF, NF);

    // GEMM1 (3-product, accurate): y = x @ W1 + b1, fp16-pair output
    gemm1_f16x3<<<dim3(D1 / BN, NROW / BM), 128, G1_SMEM>>>(
        xh, xl, w1h, w1l, b1, yh, yl, NROW, D1, CIN);

    zero_a_kernel<<<(Bn * NF + 255) / 256, 256>>>();
    reduce_a_kernel<<<dim3(HW / 64, Bn), NF>>>();
    gating_kernel<<<Bn, 768>>>(Wg1, Wg2);
    combine_kernel<<<dim3(HW / 64, Bn), NF>>>();

    // GEMM2 (2-product): out = combined @ W2 + b2
    gemm2_f16x2<<<dim3(NF / BN, NROW / BM), 128, G2_SMEM>>>(
        oc, w2h, w2l, b2, out, NROW, NF, NF);
}

// round 9
// speedup vs baseline: 1.1474x; 1.0744x over previous
#include <cuda_runtime.h>
#include <cuda_fp16.h>
#include <cstdint>
#include <math.h>

// ---------------- problem constants ----------------
#define Bn   16
#define Hh   56
#define Ww   56
#define HW   (Hh*Ww)          // 3136
#define NROW (Bn*HW)          // 50176
#define CIN  384
#define NF   384
#define KK   3
#define D1   (NF*KK)          // 1152

// ---------------- device scratch ----------------
__device__ __half  g_yh[(size_t)NROW * D1];     // y hi
__device__ __half  g_yl[(size_t)NROW * D1];     // y lo
__device__ __half  g_xh[(size_t)NROW * CIN];    // x hi
__device__ __half  g_xl[(size_t)NROW * CIN];    // x lo
__device__ __half  g_oc[(size_t)NROW * NF];     // combined (single fp16)
__device__ __half  g_w1h[(size_t)D1 * CIN];     // W1^T hi  [N,K]
__device__ __half  g_w1l[(size_t)D1 * CIN];
__device__ __half  g_w2h[(size_t)NF * NF];      // W2^T hi
__device__ __half  g_w2l[(size_t)NF * NF];
__device__ float g_a[Bn * NF];
__device__ float g_abar[Bn * D1];

// ---------------- helpers ----------------
__device__ __forceinline__ uint32_t smem_u32(const void* p) {
    uint32_t a;
    asm("{ .reg .u64 t; cvta.to.shared.u64 t, %1; cvt.u32.u64 %0, t; }" : "=r"(a) : "l"(p));
    return a;
}
__device__ __forceinline__ void cp16(uint32_t s, const void* g) {
    asm volatile("cp.async.cg.shared.global [%0], [%1], 16;" :: "r"(s), "l"(g));
}
__device__ __forceinline__ void ldsm_x4(uint32_t& r0, uint32_t& r1, uint32_t& r2,
                                        uint32_t& r3, uint32_t addr) {
    asm volatile("ldmatrix.sync.aligned.m8n8.x4.shared.b16 {%0,%1,%2,%3}, [%4];"
                 : "=r"(r0), "=r"(r1), "=r"(r2), "=r"(r3) : "r"(addr));
}
__device__ __forceinline__ void mma_f16(float* d, const uint32_t* a,
                                        uint32_t b0, uint32_t b1) {
    asm volatile("mma.sync.aligned.m16n8k16.row.col.f32.f16.f16.f32 "
        "{%0,%1,%2,%3}, {%4,%5,%6,%7}, {%8,%9}, {%0,%1,%2,%3};"
        : "+f"(d[0]), "+f"(d[1]), "+f"(d[2]), "+f"(d[3])
        : "r"(a[0]), "r"(a[1]), "r"(a[2]), "r"(a[3]), "r"(b0), "r"(b1));
}

#define BM 128
#define BN 128
#define BK 32
#define PITCH 80
#define T_BYTES (128 * PITCH)          // 10240

// ==================== GEMM1: fp16 3-product, fp16-pair output ====================
#define G1_OFF_AH 0
#define G1_OFF_AL (T_BYTES)
#define G1_OFF_BH (2 * T_BYTES)
#define G1_OFF_BL (3 * T_BYTES)
#define G1_STAGE (4 * T_BYTES)         // 40960
#define G1_SMEM (2 * G1_STAGE)         // 81920

__device__ __forceinline__ void g1_load_stage(
    uint32_t stg, const __half* Ah, const __half* Al,
    const __half* Bh, const __half* Bl,
    int bm0, int bn0, int k0, int K, int tid)
{
    #pragma unroll
    for (int t = 0; t < 4; ++t) {
        int idx = tid + t * 128;
        int r = idx >> 2, c = idx & 3;
        uint32_t so = r * PITCH + c * 16;
        size_t ga = (size_t)(bm0 + r) * K + k0 + c * 8;
        cp16(stg + G1_OFF_AH + so, Ah + ga);
        cp16(stg + G1_OFF_AL + so, Al + ga);
        size_t gb = (size_t)(bn0 + r) * K + k0 + c * 8;
        cp16(stg + G1_OFF_BH + so, Bh + gb);
        cp16(stg + G1_OFF_BL + so, Bl + gb);
    }
}

__global__ __launch_bounds__(128, 2)
void gemm1_f16x3(const __half* __restrict__ Ah,
                 const __half* __restrict__ Al,
                 const __half* __restrict__ Bh,
                 const __half* __restrict__ Bl,
                 const float* __restrict__ bias,
                 __half* __restrict__ Ch, __half* __restrict__ Cl,
                 int M, int N, int K)
{
    extern __shared__ char smem[];
    const uint32_t sbase = smem_u32(smem);
    const int tid = threadIdx.x, wid = tid >> 5, lane = tid & 31;
    const int warp_m = wid >> 1, warp_n = wid & 1;
    const int bn0 = blockIdx.x * BN, bm0 = blockIdx.y * BM;
    const int NC = K / BK;

    float acc[4][8][4] = {};

    const int a_r = (lane & 15);
    const int a_kb = ((lane >> 4) << 3) * 2;
    const int b_r = ((lane >> 4) << 3) + (lane & 7);
    const int b_kb = (((lane >> 3) & 1) << 3) * 2;

    g1_load_stage(sbase, Ah, Al, Bh, Bl, bm0, bn0, 0, K, tid);
    asm volatile("cp.async.commit_group;" ::: "memory");

    for (int c = 0; c < NC; ++c) {
        // Single barrier per chunk: wait own data, sync (orders everyone's
        // compute(c-1) reads before the prefetch writes below), prefetch, compute.
        asm volatile("cp.async.wait_group 0;" ::: "memory");
        __syncthreads();
        if (c + 1 < NC) {
            g1_load_stage(sbase + ((c + 1) & 1) * G1_STAGE,
                          Ah, Al, Bh, Bl, bm0, bn0, (c + 1) * BK, K, tid);
            asm volatile("cp.async.commit_group;" ::: "memory");
        }

        const uint32_t stg = sbase + (c & 1) * G1_STAGE;
        #pragma unroll
        for (int ks = 0; ks < 2; ++ks) {
            const int koff = ks * 32;
            uint32_t ah[4][4], al[4][4], bh[4][4], bl[4][4];
            #pragma unroll
            for (int i = 0; i < 4; ++i) {
                uint32_t ra = (warp_m * 64 + i * 16 + a_r) * PITCH + koff + a_kb;
                ldsm_x4(ah[i][0], ah[i][1], ah[i][2], ah[i][3], stg + G1_OFF_AH + ra);
                ldsm_x4(al[i][0], al[i][1], al[i][2], al[i][3], stg + G1_OFF_AL + ra);
            }
            #pragma unroll
            for (int jp = 0; jp < 4; ++jp) {
                uint32_t rb = (warp_n * 64 + jp * 16 + b_r) * PITCH + koff + b_kb;
                ldsm_x4(bh[jp][0], bh[jp][1], bh[jp][2], bh[jp][3], stg + G1_OFF_BH + rb);
                ldsm_x4(bl[jp][0], bl[jp][1], bl[jp][2], bl[jp][3], stg + G1_OFF_BL + rb);
            }
            #pragma unroll
            for (int i = 0; i < 4; ++i)
                #pragma unroll
                for (int j = 0; j < 8; ++j) {
                    const int jp = j >> 1, jj = j & 1;
                    mma_f16(acc[i][j], ah[i], bh[jp][jj * 2], bh[jp][jj * 2 + 1]);
                    mma_f16(acc[i][j], ah[i], bl[jp][jj * 2], bl[jp][jj * 2 + 1]);
                    mma_f16(acc[i][j], al[i], bh[jp][jj * 2], bh[jp][jj * 2 + 1]);
                }
        }
    }

    #pragma unroll
    for (int i = 0; i < 4; ++i) {
        int row0 = bm0 + warp_m * 64 + i * 16 + (lane >> 2);
        #pragma unroll
        for (int j = 0; j < 8; ++j) {
            int col = bn0 + warp_n * 64 + j * 8 + (lane & 3) * 2;
            float b0 = bias[col], b1 = bias[col + 1];
            float v00 = acc[i][j][0] + b0, v01 = acc[i][j][1] + b1;
            float v10 = acc[i][j][2] + b0, v11 = acc[i][j][3] + b1;
            __half h00 = __float2half_rn(v00), h01 = __float2half_rn(v01);
            __half h10 = __float2half_rn(v10), h11 = __float2half_rn(v11);
            __half l00 = __float2half_rn(v00 - __half2float(h00));
            __half l01 = __float2half_rn(v01 - __half2float(h01));
            __half l10 = __float2half_rn(v10 - __half2float(h10));
            __half l11 = __float2half_rn(v11 - __half2float(h11));
            *reinterpret_cast<__half2*>(Ch + (size_t)row0 * N + col)       = __half2{h00, h01};
            *reinterpret_cast<__half2*>(Ch + (size_t)(row0 + 8) * N + col) = __half2{h10, h11};
            *reinterpret_cast<__half2*>(Cl + (size_t)row0 * N + col)       = __half2{l00, l01};
            *reinterpret_cast<__half2*>(Cl + (size_t)(row0 + 8) * N + col) = __half2{l10, l11};
        }
    }
}

// ==================== GEMM2: fp16 2-product, fp32 output ====================
#define G2_OFF_A  0
#define G2_OFF_BH (T_BYTES)
#define G2_OFF_BL (2 * T_BYTES)
#define G2_STAGE (3 * T_BYTES)         // 30720
#define G2_NSTAGE 3
#define G2_SMEM (G2_NSTAGE * G2_STAGE) // 92160

__device__ __forceinline__ void g2_load_stage(
    uint32_t stg, const __half* A, const __half* Bh, const __half* Bl,
    int bm0, int bn0, int k0, int K, int tid)
{
    #pragma unroll
    for (int t = 0; t < 4; ++t) {
        int idx = tid + t * 128;
        int r = idx >> 2, c = idx & 3;
        uint32_t so = r * PITCH + c * 16;
        size_t ga = (size_t)(bm0 + r) * K + k0 + c * 8;
        cp16(stg + G2_OFF_A + so, A + ga);
        size_t gb = (size_t)(bn0 + r) * K + k0 + c * 8;
        cp16(stg + G2_OFF_BH + so, Bh + gb);
        cp16(stg + G2_OFF_BL + so, Bl + gb);
    }
}

__global__ __launch_bounds__(128, 2)
void gemm2_f16x2(const __half* __restrict__ A,
                 const __half* __restrict__ Bh,
                 const __half* __restrict__ Bl,
                 const float* __restrict__ bias,
                 float* __restrict__ C, int M, int N, int K)
{
    extern __shared__ char smem[];
    const uint32_t sbase = smem_u32(smem);
    const int tid = threadIdx.x, wid = tid >> 5, lane = tid & 31;
    const int warp_m = wid >> 1, warp_n = wid & 1;
    const int bn0 = blockIdx.x * BN, bm0 = blockIdx.y * BM;
    const int NC = K / BK;

    float acc[4][8][4] = {};

    const int a_r = (lane & 15);
    const int a_kb = ((lane >> 4) << 3) * 2;
    const int b_r = ((lane >> 4) << 3) + (lane & 7);
    const int b_kb = (((lane >> 3) & 1) << 3) * 2;

    g2_load_stage(sbase + 0 * G2_STAGE, A, Bh, Bl, bm0, bn0, 0, K, tid);
    asm volatile("cp.async.commit_group;" ::: "memory");
    g2_load_stage(sbase + 1 * G2_STAGE, A, Bh, Bl, bm0, bn0, BK, K, tid);
    asm volatile("cp.async.commit_group;" ::: "memory");

    for (int c = 0; c < NC; ++c) {
        // wait group(c): with <=2 outstanding, allow the newest one
        if (c + 1 < NC) {
            asm volatile("cp.async.wait_group 1;" ::: "memory");
        } else {
            asm volatile("cp.async.wait_group 0;" ::: "memory");
        }
        __syncthreads();
        if (c + 2 < NC) {
            int nb = (c + 2) % G2_NSTAGE;
            g2_load_stage(sbase + nb * G2_STAGE, A, Bh, Bl, bm0, bn0, (c + 2) * BK, K, tid);
            asm volatile("cp.async.commit_group;" ::: "memory");
        }

        const uint32_t stg = sbase + (c % G2_NSTAGE) * G2_STAGE;
        #pragma unroll
        for (int ks = 0; ks < 2; ++ks) {
            const int koff = ks * 32;
            uint32_t a[4][4], bh[4][4], bl[4][4];
            #pragma unroll
            for (int i = 0; i < 4; ++i) {
                uint32_t ra = (warp_m * 64 + i * 16 + a_r) * PITCH + koff + a_kb;
                ldsm_x4(a[i][0], a[i][1], a[i][2], a[i][3], stg + G2_OFF_A + ra);
            }
            #pragma unroll
            for (int jp = 0; jp < 4; ++jp) {
                uint32_t rb = (warp_n * 64 + jp * 16 + b_r) * PITCH + koff + b_kb;
                ldsm_x4(bh[jp][0], bh[jp][1], bh[jp][2], bh[jp][3], stg + G2_OFF_BH + rb);
                ldsm_x4(bl[jp][0], bl[jp][1], bl[jp][2], bl[jp][3], stg + G2_OFF_BL + rb);
            }
            #pragma unroll
            for (int i = 0; i < 4; ++i)
                #pragma unroll
                for (int j = 0; j < 8; ++j) {
                    const int jp = j >> 1, jj = j & 1;
                    mma_f16(acc[i][j], a[i], bh[jp][jj * 2], bh[jp][jj * 2 + 1]);
                    mma_f16(acc[i][j], a[i], bl[jp][jj * 2], bl[jp][jj * 2 + 1]);
                }
        }
    }

    #pragma unroll
    for (int i = 0; i < 4; ++i) {
        int row0 = bm0 + warp_m * 64 + i * 16 + (lane >> 2);
        #pragma unroll
        for (int j = 0; j < 8; ++j) {
            int col = bn0 + warp_n * 64 + j * 8 + (lane & 3) * 2;
            float b0 = bias[col], b1 = bias[col + 1];
            float2 v0 = {acc[i][j][0] + b0, acc[i][j][1] + b1};
            float2 v1 = {acc[i][j][2] + b0, acc[i][j][3] + b1};
            *reinterpret_cast<float2*>(C + (size_t)row0 * N + col) = v0;
            *reinterpret_cast<float2*>(C + (size_t)(row0 + 8) * N + col) = v1;
        }
    }
}

// ---------------- conversion kernels ----------------
__global__ __launch_bounds__(256)
void splitx_kernel(const float* __restrict__ src,
                   __half* __restrict__ h, __half* __restrict__ l, int n4) {
    // piggyback: zero g_a (first 24 blocks cover 16*384 floats)
    if (blockIdx.x < 24) {
        int z = blockIdx.x * 256 + threadIdx.x;
        if (z < Bn * NF) g_a[z] = 0.0f;
    }
    int i = blockIdx.x * blockDim.x + threadIdx.x;
    if (i >= n4) return;
    float4 v = reinterpret_cast<const float4*>(src)[i];
    __half h0 = __float2half_rn(v.x), h1 = __float2half_rn(v.y);
    __half h2 = __float2half_rn(v.z), h3 = __float2half_rn(v.w);
    __half l0 = __float2half_rn(v.x - __half2float(h0));
    __half l1 = __float2half_rn(v.y - __half2float(h1));
    __half l2 = __float2half_rn(v.z - __half2float(h2));
    __half l3 = __float2half_rn(v.w - __half2float(h3));
    __half2* hp = reinterpret_cast<__half2*>(h);
    __half2* lp = reinterpret_cast<__half2*>(l);
    hp[2 * i]     = __half2{h0, h1};
    hp[2 * i + 1] = __half2{h2, h3};
    lp[2 * i]     = __half2{l0, l1};
    lp[2 * i + 1] = __half2{l2, l3};
}

__global__ void wsplit_kernel(const float* __restrict__ W,
                              __half* __restrict__ Oh, __half* __restrict__ Ol,
                              int K, int N) {
    __shared__ float t[32][33];
    int n0 = blockIdx.x * 32, k0 = blockIdx.y * 32;
    int tx = threadIdx.x, ty = threadIdx.y;
    #pragma unroll
    for (int r = 0; r < 4; r++)
        t[ty + 8 * r][tx] = W[(size_t)(k0 + ty + 8 * r) * N + n0 + tx];
    __syncthreads();
    #pragma unroll
    for (int r = 0; r < 4; r++) {
        int n = n0 + ty + 8 * r, k = k0 + tx;
        float v = t[tx][ty + 8 * r];
        __half h = __float2half_rn(v);
        __half l = __float2half_rn(v - __half2float(h));
        Oh[(size_t)n * K + k] = h;
        Ol[(size_t)n * K + k] = l;
    }
}

// ---------------- shift / gating path ----------------
__device__ __forceinline__ int shift_src(int mode, int q, int h, int w) {
    int hh = h, ww = w;
    if (mode == 1) {
        if      (q == 0) ww = max(w - 1, 0);
        else if (q == 1) ww = min(w + 1, Ww - 1);
        else if (q == 2) hh = max(h - 1, 0);
        else             hh = min(h + 1, Hh - 1);
    } else {
        if      (q == 0) hh = max(h - 1, 0);
        else if (q == 1) hh = min(h + 1, Hh - 1);
        else if (q == 2) ww = max(w - 1, 0);
        else             ww = min(w + 1, Ww - 1);
    }
    return hh * Ww + ww;
}

// 192 threads: each handles a channel PAIR via __half2 (quarters are 96-wide,
// pairs never straddle a quarter). Reads y-hi only.
__global__ __launch_bounds__(192)
void reduce_a_kernel() {
    const int b = blockIdx.y, chunk = blockIdx.x, tp = threadIdx.x;
    const int c0 = 2 * tp;
    const int q = c0 / (NF / 4);
    const __half2* yb = reinterpret_cast<const __half2*>(g_yh) + (size_t)b * HW * (D1 / 2);
    float acc0 = 0.0f, acc1 = 0.0f;
    for (int j = 0; j < 64; j++) {
        int hw = chunk * 64 + j;
        int h = hw / Ww, w = hw % Ww;
        int s1 = shift_src(1, q, h, w);
        int s2 = shift_src(2, q, h, w);
        __half2 v1 = yb[(size_t)s1 * (D1 / 2) + tp];
        __half2 v2 = yb[(size_t)s2 * (D1 / 2) + (NF / 2) + tp];
        __half2 v3 = yb[(size_t)hw * (D1 / 2) + NF + tp];
        acc0 += __low2float(v1) + __low2float(v2) + __low2float(v3);
        acc1 += __high2float(v1) + __high2float(v2) + __high2float(v3);
    }
    atomicAdd(&g_a[b * NF + c0], acc0);
    atomicAdd(&g_a[b * NF + c0 + 1], acc1);
}

__device__ __forceinline__ float gelu_t(float x) {
    float t = tanhf(0.7978845608028654f * (x + 0.044715f * x * x * x));
    return 0.5f * x * (1.0f + t);
}

__global__ __launch_bounds__(768)
void gating_kernel(const float* __restrict__ Wg1, const float* __restrict__ Wg2) {
    __shared__ float a_s[NF];
    __shared__ float h_s[NF];
    __shared__ float part[2][NF];
    const int b = blockIdx.x;
    const int tid = threadIdx.x;
    const int half = tid / NF;
    const int cc = tid - half * NF;
    if (tid < NF) a_s[tid] = g_a[b * NF + tid];
    __syncthreads();

    {
        float s = 0.0f;
        const int i0 = half * (NF / 2);
        #pragma unroll 16
        for (int j = 0; j < NF / 2; j++)
            s += a_s[i0 + j] * Wg1[(size_t)(i0 + j) * NF + cc];
        part[half][cc] = s;
    }
    __syncthreads();
    if (tid < NF) h_s[tid] = gelu_t(part[0][tid] + part[1][tid]);
    __syncthreads();

    float s0 = 0.0f, s1 = 0.0f, s2 = 0.0f;
    {
        const int i0 = half * (NF / 2);
        #pragma unroll 8
        for (int j = 0; j < NF / 2; j++) {
            float hv = h_s[i0 + j];
            const float* w = Wg2 + (size_t)(i0 + j) * D1 + cc;
            s0 += hv * w[0];
            s1 += hv * w[NF];
            s2 += hv * w[2 * NF];
        }
    }
    part[half][cc] = s0; __syncthreads();
    float a0 = (tid < NF) ? part[0][tid] + part[1][tid] : 0.0f; __syncthreads();
    part[half][cc] = s1; __syncthreads();
    float a1 = (tid < NF) ? part[0][tid] + part[1][tid] : 0.0f; __syncthreads();
    part[half][cc] = s2; __syncthreads();
    float a2 = (tid < NF) ? part[0][tid] + part[1][tid] : 0.0f;

    if (tid < NF) {
        float m = fmaxf(a0, fmaxf(a1, a2));
        float e0 = expf(a0 - m), e1 = expf(a1 - m), e2 = expf(a2 - m);
        float inv = 1.0f / (e0 + e1 + e2);
        g_abar[b * D1 + tid] = e0 * inv;
        g_abar[b * D1 + NF + tid] = e1 * inv;
        g_abar[b * D1 + 2 * NF + tid] = e2 * inv;
    }
}

// 192 threads, channel-pair per thread; reads y hi+lo pairs, writes single fp16
__global__ __launch_bounds__(192)
void combine_kernel() {
    __shared__ float ab[D1];
    const int b = blockIdx.y, chunk = blockIdx.x, tp = threadIdx.x;
    for (int i = tp; i < D1; i += 192) ab[i] = g_abar[b * D1 + i];
    __syncthreads();

    const int c0 = 2 * tp;
    const int q = c0 / (NF / 4);
    const float a0l = ab[c0],          a0h = ab[c0 + 1];
    const float a1l = ab[NF + c0],     a1h = ab[NF + c0 + 1];
    const float a2l = ab[2 * NF + c0], a2h = ab[2 * NF + c0 + 1];
    const __half2* yh = reinterpret_cast<const __half2*>(g_yh) + (size_t)b * HW * (D1 / 2);
    const __half2* yl = reinterpret_cast<const __half2*>(g_yl) + (size_t)b * HW * (D1 / 2);
    __half2* oc = reinterpret_cast<__half2*>(g_oc) + (size_t)b * HW * (NF / 2);

    for (int j = 0; j < 64; j++) {
        int hw = chunk * 64 + j;
        int h = hw / Ww, w = hw % Ww;
        int s1 = shift_src(1, q, h, w);
        int s2 = shift_src(2, q, h, w);
        size_t i1 = (size_t)s1 * (D1 / 2) + tp;
        size_t i2 = (size_t)s2 * (D1 / 2) + (NF / 2) + tp;
        size_t i3 = (size_t)hw * (D1 / 2) + NF + tp;
        __half2 h1 = yh[i1], l1 = yl[i1];
        __half2 h2 = yh[i2], l2 = yl[i2];
        __half2 h3 = yh[i3], l3 = yl[i3];
        float vl = a0l * (__low2float(h1) + __low2float(l1))
                 + a1l * (__low2float(h2) + __low2float(l2))
                 + a2l * (__low2float(h3) + __low2float(l3));
        float vh = a0h * (__high2float(h1) + __high2float(l1))
                 + a1h * (__high2float(h2) + __high2float(l2))
                 + a2h * (__high2float(h3) + __high2float(l3));
        oc[(size_t)hw * (NF / 2) + tp] = __half2{__float2half_rn(vl), __float2half_rn(vh)};
    }
}

// ---------------- launch ----------------
extern "C" void kernel_launch(void* const* d_in, const int* in_sizes, int n_in,
                              void* d_out, int out_size) {
    const float* x   = (const float*)d_in[0];
    const float* W1  = (const float*)d_in[1];
    const float* b1  = (const float*)d_in[2];
    const float* Wg1 = (const float*)d_in[3];
    const float* Wg2 = (const float*)d_in[4];
    const float* W2  = (const float*)d_in[5];
    const float* b2  = (const float*)d_in[6];
    float* out = (float*)d_out;

    __half *yh, *yl, *xh, *xl, *oc, *w1h, *w1l, *w2h, *w2l;
    cudaGetSymbolAddress((void**)&yh, g_yh);
    cudaGetSymbolAddress((void**)&yl, g_yl);
    cudaGetSymbolAddress((void**)&xh, g_xh);
    cudaGetSymbolAddress((void**)&xl, g_xl);
    cudaGetSymbolAddress((void**)&oc, g_oc);
    cudaGetSymbolAddress((void**)&w1h, g_w1h);
    cudaGetSymbolAddress((void**)&w1l, g_w1l);
    cudaGetSymbolAddress((void**)&w2h, g_w2h);
    cudaGetSymbolAddress((void**)&w2l, g_w2l);

    cudaFuncSetAttribute(gemm1_f16x3,
                         cudaFuncAttributeMaxDynamicSharedMemorySize, G1_SMEM);
    cudaFuncSetAttribute(gemm2_f16x2,
                         cudaFuncAttributeMaxDynamicSharedMemorySize, G2_SMEM);

    splitx_kernel<<<(NROW * CIN / 4 + 255) / 256, 256>>>(x, xh, xl, NROW * CIN / 4);
    wsplit_kernel<<<dim3(D1 / 32, CIN / 32), dim3(32, 8)>>>(W1, w1h, w1l, CIN, D1);
    wsplit_kernel<<<dim3(NF / 32, NF / 32), dim3(32, 8)>>>(W2, w2h, w2l, NF, NF);

    gemm1_f16x3<<<dim3(D1 / BN, NROW / BM), 128, G1_SMEM>>>(
        xh, xl, w1h, w1l, b1, yh, yl, NROW, D1, CIN);

    reduce_a_kernel<<<dim3(HW / 64, Bn), 192>>>();
    gating_kernel<<<Bn, 768>>>(Wg1, Wg2);
    combine_kernel<<<dim3(HW / 64, Bn), 192>>>();

    gemm2_f16x2<<<dim3(NF / BN, NROW / BM), 128, G2_SMEM>>>(
        oc, w2h, w2l, b2, out, NROW, NF, NF);
}

// round 10
// speedup vs baseline: 1.1489x; 1.0013x over previous
#include <cuda_runtime.h>
#include <cuda_fp16.h>
#include <cstdint>
#include <math.h>

// ---------------- problem constants ----------------
#define Bn   16
#define Hh   56
#define Ww   56
#define HW   (Hh*Ww)          // 3136
#define NROW (Bn*HW)          // 50176
#define CIN  384
#define NF   384
#define KK   3
#define D1   (NF*KK)          // 1152

// ---------------- device scratch ----------------
__device__ __half  g_yh[(size_t)NROW * D1];
__device__ __half  g_yl[(size_t)NROW * D1];
__device__ __half  g_xh[(size_t)NROW * CIN];
__device__ __half  g_xl[(size_t)NROW * CIN];
__device__ __half  g_oc[(size_t)NROW * NF];
__device__ __half  g_w1h[(size_t)D1 * CIN];
__device__ __half  g_w1l[(size_t)D1 * CIN];
__device__ __half  g_w2h[(size_t)NF * NF];
__device__ __half  g_w2l[(size_t)NF * NF];
__device__ float g_a[Bn * NF];
__device__ float g_abar[Bn * D1];

// ---------------- helpers ----------------
__device__ __forceinline__ uint32_t smem_u32(const void* p) {
    uint32_t a;
    asm("{ .reg .u64 t; cvta.to.shared.u64 t, %1; cvt.u32.u64 %0, t; }" : "=r"(a) : "l"(p));
    return a;
}
__device__ __forceinline__ void cp16(uint32_t s, const void* g) {
    asm volatile("cp.async.cg.shared.global [%0], [%1], 16;" :: "r"(s), "l"(g));
}
__device__ __forceinline__ void ldsm_x4(uint32_t& r0, uint32_t& r1, uint32_t& r2,
                                        uint32_t& r3, uint32_t addr) {
    asm volatile("ldmatrix.sync.aligned.m8n8.x4.shared.b16 {%0,%1,%2,%3}, [%4];"
                 : "=r"(r0), "=r"(r1), "=r"(r2), "=r"(r3) : "r"(addr));
}
__device__ __forceinline__ void mma_f16(float* d, const uint32_t* a,
                                        uint32_t b0, uint32_t b1) {
    asm volatile("mma.sync.aligned.m16n8k16.row.col.f32.f16.f16.f32 "
        "{%0,%1,%2,%3}, {%4,%5,%6,%7}, {%8,%9}, {%0,%1,%2,%3};"
        : "+f"(d[0]), "+f"(d[1]), "+f"(d[2]), "+f"(d[3])
        : "r"(a[0]), "r"(a[1]), "r"(a[2]), "r"(a[3]), "r"(b0), "r"(b1));
}

// CTA tile 256x128xBK64, 256 threads (8 warps, 4x2), warp tile 64x64.
#define BM 256
#define BN 128
#define BK 64
#define PITCH 144                       // 64 fp16 = 128B + 16B pad, 16B-aligned
#define A_BYTES (BM * PITCH)            // 36864
#define B_BYTES (BN * PITCH)            // 18432

// ==================== GEMM1: fp16 3-product, fp16-pair output ====================
#define G1_OFF_AH 0
#define G1_OFF_AL (A_BYTES)
#define G1_OFF_BH (2 * A_BYTES)
#define G1_OFF_BL (2 * A_BYTES + B_BYTES)
#define G1_STAGE  (2 * A_BYTES + 2 * B_BYTES)   // 110592
#define G1_SMEM   (2 * G1_STAGE)                // 221184

__device__ __forceinline__ void g1_load_stage(
    uint32_t stg, const __half* Ah, const __half* Al,
    const __half* Bh, const __half* Bl,
    int bm0, int bn0, int k0, int K, int tid)
{
    #pragma unroll
    for (int t = 0; t < 8; ++t) {               // A: 2048 16B-chunks per array
        int idx = tid + t * 256;
        int r = idx >> 3, c = idx & 7;
        uint32_t so = r * PITCH + c * 16;
        size_t ga = (size_t)(bm0 + r) * K + k0 + c * 8;
        cp16(stg + G1_OFF_AH + so, Ah + ga);
        cp16(stg + G1_OFF_AL + so, Al + ga);
    }
    #pragma unroll
    for (int t = 0; t < 4; ++t) {               // B: 1024 chunks per array
        int idx = tid + t * 256;
        int r = idx >> 3, c = idx & 7;
        uint32_t so = r * PITCH + c * 16;
        size_t gb = (size_t)(bn0 + r) * K + k0 + c * 8;
        cp16(stg + G1_OFF_BH + so, Bh + gb);
        cp16(stg + G1_OFF_BL + so, Bl + gb);
    }
}

__global__ __launch_bounds__(256, 1)
void gemm1_f16x3(const __half* __restrict__ Ah,
                 const __half* __restrict__ Al,
                 const __half* __restrict__ Bh,
                 const __half* __restrict__ Bl,
                 const float* __restrict__ bias,
                 __half* __restrict__ Ch, __half* __restrict__ Cl,
                 int M, int N, int K)
{
    extern __shared__ char smem[];
    const uint32_t sbase = smem_u32(smem);
    const int tid = threadIdx.x, wid = tid >> 5, lane = tid & 31;
    const int warp_m = wid >> 1, warp_n = wid & 1;     // 4 x 2
    const int bn0 = blockIdx.x * BN, bm0 = blockIdx.y * BM;
    const int NC = K / BK;                              // 6

    float acc[4][8][4] = {};

    const int a_r = (lane & 15);
    const int a_kb = (lane >> 4) * 16;
    const int b_r = ((lane >> 4) << 3) + (lane & 7);
    const int b_kb = ((lane >> 3) & 1) * 16;

    g1_load_stage(sbase, Ah, Al, Bh, Bl, bm0, bn0, 0, K, tid);
    asm volatile("cp.async.commit_group;" ::: "memory");

    for (int c = 0; c < NC; ++c) {
        asm volatile("cp.async.wait_group 0;" ::: "memory");
        __syncthreads();
        if (c + 1 < NC) {
            g1_load_stage(sbase + ((c + 1) & 1) * G1_STAGE,
                          Ah, Al, Bh, Bl, bm0, bn0, (c + 1) * BK, K, tid);
            asm volatile("cp.async.commit_group;" ::: "memory");
        }

        const uint32_t stg = sbase + (c & 1) * G1_STAGE;
        #pragma unroll
        for (int ks = 0; ks < 4; ++ks) {
            const int koff = ks * 32;
            uint32_t ah[4][4], al[4][4], bh[4][4], bl[4][4];
            #pragma unroll
            for (int i = 0; i < 4; ++i) {
                uint32_t ra = (warp_m * 64 + i * 16 + a_r) * PITCH + koff + a_kb;
                ldsm_x4(ah[i][0], ah[i][1], ah[i][2], ah[i][3], stg + G1_OFF_AH + ra);
                ldsm_x4(al[i][0], al[i][1], al[i][2], al[i][3], stg + G1_OFF_AL + ra);
            }
            #pragma unroll
            for (int jp = 0; jp < 4; ++jp) {
                uint32_t rb = (warp_n * 64 + jp * 16 + b_r) * PITCH + koff + b_kb;
                ldsm_x4(bh[jp][0], bh[jp][1], bh[jp][2], bh[jp][3], stg + G1_OFF_BH + rb);
                ldsm_x4(bl[jp][0], bl[jp][1], bl[jp][2], bl[jp][3], stg + G1_OFF_BL + rb);
            }
            #pragma unroll
            for (int i = 0; i < 4; ++i)
                #pragma unroll
                for (int j = 0; j < 8; ++j) {
                    const int jp = j >> 1, jj = j & 1;
                    mma_f16(acc[i][j], ah[i], bh[jp][jj * 2], bh[jp][jj * 2 + 1]);
                    mma_f16(acc[i][j], ah[i], bl[jp][jj * 2], bl[jp][jj * 2 + 1]);
                    mma_f16(acc[i][j], al[i], bh[jp][jj * 2], bh[jp][jj * 2 + 1]);
                }
        }
    }

    #pragma unroll
    for (int i = 0; i < 4; ++i) {
        int row0 = bm0 + warp_m * 64 + i * 16 + (lane >> 2);
        #pragma unroll
        for (int j = 0; j < 8; ++j) {
            int col = bn0 + warp_n * 64 + j * 8 + (lane & 3) * 2;
            float b0 = bias[col], b1 = bias[col + 1];
            float v00 = acc[i][j][0] + b0, v01 = acc[i][j][1] + b1;
            float v10 = acc[i][j][2] + b0, v11 = acc[i][j][3] + b1;
            __half h00 = __float2half_rn(v00), h01 = __float2half_rn(v01);
            __half h10 = __float2half_rn(v10), h11 = __float2half_rn(v11);
            __half l00 = __float2half_rn(v00 - __half2float(h00));
            __half l01 = __float2half_rn(v01 - __half2float(h01));
            __half l10 = __float2half_rn(v10 - __half2float(h10));
            __half l11 = __float2half_rn(v11 - __half2float(h11));
            *reinterpret_cast<__half2*>(Ch + (size_t)row0 * N + col)       = __half2{h00, h01};
            *reinterpret_cast<__half2*>(Ch + (size_t)(row0 + 8) * N + col) = __half2{h10, h11};
            *reinterpret_cast<__half2*>(Cl + (size_t)row0 * N + col)       = __half2{l00, l01};
            *reinterpret_cast<__half2*>(Cl + (size_t)(row0 + 8) * N + col) = __half2{l10, l11};
        }
    }
}

// ==================== GEMM2: fp16 2-product, fp32 output ====================
#define G2_OFF_A  0
#define G2_OFF_BH (A_BYTES)
#define G2_OFF_BL (A_BYTES + B_BYTES)
#define G2_STAGE  (A_BYTES + 2 * B_BYTES)   // 73728
#define G2_SMEM   (2 * G2_STAGE)            // 147456

__device__ __forceinline__ void g2_load_stage(
    uint32_t stg, const __half* A, const __half* Bh, const __half* Bl,
    int bm0, int bn0, int k0, int K, int tid)
{
    #pragma unroll
    for (int t = 0; t < 8; ++t) {
        int idx = tid + t * 256;
        int r = idx >> 3, c = idx & 7;
        uint32_t so = r * PITCH + c * 16;
        size_t ga = (size_t)(bm0 + r) * K + k0 + c * 8;
        cp16(stg + G2_OFF_A + so, A + ga);
    }
    #pragma unroll
    for (int t = 0; t < 4; ++t) {
        int idx = tid + t * 256;
        int r = idx >> 3, c = idx & 7;
        uint32_t so = r * PITCH + c * 16;
        size_t gb = (size_t)(bn0 + r) * K + k0 + c * 8;
        cp16(stg + G2_OFF_BH + so, Bh + gb);
        cp16(stg + G2_OFF_BL + so, Bl + gb);
    }
}

__global__ __launch_bounds__(256, 1)
void gemm2_f16x2(const __half* __restrict__ A,
                 const __half* __restrict__ Bh,
                 const __half* __restrict__ Bl,
                 const float* __restrict__ bias,
                 float* __restrict__ C, int M, int N, int K)
{
    extern __shared__ char smem[];
    const uint32_t sbase = smem_u32(smem);
    const int tid = threadIdx.x, wid = tid >> 5, lane = tid & 31;
    const int warp_m = wid >> 1, warp_n = wid & 1;
    const int bn0 = blockIdx.x * BN, bm0 = blockIdx.y * BM;
    const int NC = K / BK;

    float acc[4][8][4] = {};

    const int a_r = (lane & 15);
    const int a_kb = (lane >> 4) * 16;
    const int b_r = ((lane >> 4) << 3) + (lane & 7);
    const int b_kb = ((lane >> 3) & 1) * 16;

    g2_load_stage(sbase, A, Bh, Bl, bm0, bn0, 0, K, tid);
    asm volatile("cp.async.commit_group;" ::: "memory");

    for (int c = 0; c < NC; ++c) {
        asm volatile("cp.async.wait_group 0;" ::: "memory");
        __syncthreads();
        if (c + 1 < NC) {
            g2_load_stage(sbase + ((c + 1) & 1) * G2_STAGE,
                          A, Bh, Bl, bm0, bn0, (c + 1) * BK, K, tid);
            asm volatile("cp.async.commit_group;" ::: "memory");
        }

        const uint32_t stg = sbase + (c & 1) * G2_STAGE;
        #pragma unroll
        for (int ks = 0; ks < 4; ++ks) {
            const int koff = ks * 32;
            uint32_t a[4][4], bh[4][4], bl[4][4];
            #pragma unroll
            for (int i = 0; i < 4; ++i) {
                uint32_t ra = (warp_m * 64 + i * 16 + a_r) * PITCH + koff + a_kb;
                ldsm_x4(a[i][0], a[i][1], a[i][2], a[i][3], stg + G2_OFF_A + ra);
            }
            #pragma unroll
            for (int jp = 0; jp < 4; ++jp) {
                uint32_t rb = (warp_n * 64 + jp * 16 + b_r) * PITCH + koff + b_kb;
                ldsm_x4(bh[jp][0], bh[jp][1], bh[jp][2], bh[jp][3], stg + G2_OFF_BH + rb);
                ldsm_x4(bl[jp][0], bl[jp][1], bl[jp][2], bl[jp][3], stg + G2_OFF_BL + rb);
            }
            #pragma unroll
            for (int i = 0; i < 4; ++i)
                #pragma unroll
                for (int j = 0; j < 8; ++j) {
                    const int jp = j >> 1, jj = j & 1;
                    mma_f16(acc[i][j], a[i], bh[jp][jj * 2], bh[jp][jj * 2 + 1]);
                    mma_f16(acc[i][j], a[i], bl[jp][jj * 2], bl[jp][jj * 2 + 1]);
                }
        }
    }

    #pragma unroll
    for (int i = 0; i < 4; ++i) {
        int row0 = bm0 + warp_m * 64 + i * 16 + (lane >> 2);
        #pragma unroll
        for (int j = 0; j < 8; ++j) {
            int col = bn0 + warp_n * 64 + j * 8 + (lane & 3) * 2;
            float b0 = bias[col], b1 = bias[col + 1];
            float2 v0 = {acc[i][j][0] + b0, acc[i][j][1] + b1};
            float2 v1 = {acc[i][j][2] + b0, acc[i][j][3] + b1};
            *reinterpret_cast<float2*>(C + (size_t)row0 * N + col) = v0;
            *reinterpret_cast<float2*>(C + (size_t)(row0 + 8) * N + col) = v1;
        }
    }
}

// ---------------- conversion kernels ----------------
__global__ __launch_bounds__(256)
void splitx_kernel(const float* __restrict__ src,
                   __half* __restrict__ h, __half* __restrict__ l, int n4) {
    if (blockIdx.x < 24) {
        int z = blockIdx.x * 256 + threadIdx.x;
        if (z < Bn * NF) g_a[z] = 0.0f;
    }
    int i = blockIdx.x * blockDim.x + threadIdx.x;
    if (i >= n4) return;
    float4 v = reinterpret_cast<const float4*>(src)[i];
    __half h0 = __float2half_rn(v.x), h1 = __float2half_rn(v.y);
    __half h2 = __float2half_rn(v.z), h3 = __float2half_rn(v.w);
    __half l0 = __float2half_rn(v.x - __half2float(h0));
    __half l1 = __float2half_rn(v.y - __half2float(h1));
    __half l2 = __float2half_rn(v.z - __half2float(h2));
    __half l3 = __float2half_rn(v.w - __half2float(h3));
    __half2* hp = reinterpret_cast<__half2*>(h);
    __half2* lp = reinterpret_cast<__half2*>(l);
    hp[2 * i]     = __half2{h0, h1};
    hp[2 * i + 1] = __half2{h2, h3};
    lp[2 * i]     = __half2{l0, l1};
    lp[2 * i + 1] = __half2{l2, l3};
}

__global__ void wsplit_kernel(const float* __restrict__ W,
                              __half* __restrict__ Oh, __half* __restrict__ Ol,
                              int K, int N) {
    __shared__ float t[32][33];
    int n0 = blockIdx.x * 32, k0 = blockIdx.y * 32;
    int tx = threadIdx.x, ty = threadIdx.y;
    #pragma unroll
    for (int r = 0; r < 4; r++)
        t[ty + 8 * r][tx] = W[(size_t)(k0 + ty + 8 * r) * N + n0 + tx];
    __syncthreads();
    #pragma unroll
    for (int r = 0; r < 4; r++) {
        int n = n0 + ty + 8 * r, k = k0 + tx;
        float v = t[tx][ty + 8 * r];
        __half h = __float2half_rn(v);
        __half l = __float2half_rn(v - __half2float(h));
        Oh[(size_t)n * K + k] = h;
        Ol[(size_t)n * K + k] = l;
    }
}

// ---------------- shift / gating path ----------------
__device__ __forceinline__ int shift_src(int mode, int q, int h, int w) {
    int hh = h, ww = w;
    if (mode == 1) {
        if      (q == 0) ww = max(w - 1, 0);
        else if (q == 1) ww = min(w + 1, Ww - 1);
        else if (q == 2) hh = max(h - 1, 0);
        else             hh = min(h + 1, Hh - 1);
    } else {
        if      (q == 0) hh = max(h - 1, 0);
        else if (q == 1) hh = min(h + 1, Hh - 1);
        else if (q == 2) ww = max(w - 1, 0);
        else             ww = min(w + 1, Ww - 1);
    }
    return hh * Ww + ww;
}

__global__ __launch_bounds__(192)
void reduce_a_kernel() {
    const int b = blockIdx.y, chunk = blockIdx.x, tp = threadIdx.x;
    const int c0 = 2 * tp;
    const int q = c0 / (NF / 4);
    const __half2* yb = reinterpret_cast<const __half2*>(g_yh) + (size_t)b * HW * (D1 / 2);
    float acc0 = 0.0f, acc1 = 0.0f;
    for (int j = 0; j < 64; j++) {
        int hw = chunk * 64 + j;
        int h = hw / Ww, w = hw % Ww;
        int s1 = shift_src(1, q, h, w);
        int s2 = shift_src(2, q, h, w);
        __half2 v1 = yb[(size_t)s1 * (D1 / 2) + tp];
        __half2 v2 = yb[(size_t)s2 * (D1 / 2) + (NF / 2) + tp];
        __half2 v3 = yb[(size_t)hw * (D1 / 2) + NF + tp];
        acc0 += __low2float(v1) + __low2float(v2) + __low2float(v3);
        acc1 += __high2float(v1) + __high2float(v2) + __high2float(v3);
    }
    atomicAdd(&g_a[b * NF + c0], acc0);
    atomicAdd(&g_a[b * NF + c0 + 1], acc1);
}

__device__ __forceinline__ float gelu_t(float x) {
    float t = tanhf(0.7978845608028654f * (x + 0.044715f * x * x * x));
    return 0.5f * x * (1.0f + t);
}

__global__ __launch_bounds__(768)
void gating_kernel(const float* __restrict__ Wg1, const float* __restrict__ Wg2) {
    __shared__ float a_s[NF];
    __shared__ float h_s[NF];
    __shared__ float part[2][NF];
    const int b = blockIdx.x;
    const int tid = threadIdx.x;
    const int half = tid / NF;
    const int cc = tid - half * NF;
    if (tid < NF) a_s[tid] = g_a[b * NF + tid];
    __syncthreads();

    {
        float s = 0.0f;
        const int i0 = half * (NF / 2);
        #pragma unroll 16
        for (int j = 0; j < NF / 2; j++)
            s += a_s[i0 + j] * Wg1[(size_t)(i0 + j) * NF + cc];
        part[half][cc] = s;
    }
    __syncthreads();
    if (tid < NF) h_s[tid] = gelu_t(part[0][tid] + part[1][tid]);
    __syncthreads();

    float s0 = 0.0f, s1 = 0.0f, s2 = 0.0f;
    {
        const int i0 = half * (NF / 2);
        #pragma unroll 8
        for (int j = 0; j < NF / 2; j++) {
            float hv = h_s[i0 + j];
            const float* w = Wg2 + (size_t)(i0 + j) * D1 + cc;
            s0 += hv * w[0];
            s1 += hv * w[NF];
            s2 += hv * w[2 * NF];
        }
    }
    part[half][cc] = s0; __syncthreads();
    float a0 = (tid < NF) ? part[0][tid] + part[1][tid] : 0.0f; __syncthreads();
    part[half][cc] = s1; __syncthreads();
    float a1 = (tid < NF) ? part[0][tid] + part[1][tid] : 0.0f; __syncthreads();
    part[half][cc] = s2; __syncthreads();
    float a2 = (tid < NF) ? part[0][tid] + part[1][tid] : 0.0f;

    if (tid < NF) {
        float m = fmaxf(a0, fmaxf(a1, a2));
        float e0 = expf(a0 - m), e1 = expf(a1 - m), e2 = expf(a2 - m);
        float inv = 1.0f / (e0 + e1 + e2);
        g_abar[b * D1 + tid] = e0 * inv;
        g_abar[b * D1 + NF + tid] = e1 * inv;
        g_abar[b * D1 + 2 * NF + tid] = e2 * inv;
    }
}

__global__ __launch_bounds__(192)
void combine_kernel() {
    __shared__ float ab[D1];
    const int b = blockIdx.y, chunk = blockIdx.x, tp = threadIdx.x;
    for (int i = tp; i < D1; i += 192) ab[i] = g_abar[b * D1 + i];
    __syncthreads();

    const int c0 = 2 * tp;
    const int q = c0 / (NF / 4);
    const float a0l = ab[c0],          a0h = ab[c0 + 1];
    const float a1l = ab[NF + c0],     a1h = ab[NF + c0 + 1];
    const float a2l = ab[2 * NF + c0], a2h = ab[2 * NF + c0 + 1];
    const __half2* yh = reinterpret_cast<const __half2*>(g_yh) + (size_t)b * HW * (D1 / 2);
    const __half2* yl = reinterpret_cast<const __half2*>(g_yl) + (size_t)b * HW * (D1 / 2);
    __half2* oc = reinterpret_cast<__half2*>(g_oc) + (size_t)b * HW * (NF / 2);

    for (int j = 0; j < 64; j++) {
        int hw = chunk * 64 + j;
        int h = hw / Ww, w = hw % Ww;
        int s1 = shift_src(1, q, h, w);
        int s2 = shift_src(2, q, h, w);
        size_t i1 = (size_t)s1 * (D1 / 2) + tp;
        size_t i2 = (size_t)s2 * (D1 / 2) + (NF / 2) + tp;
        size_t i3 = (size_t)hw * (D1 / 2) + NF + tp;
        __half2 h1 = yh[i1], l1 = yl[i1];
        __half2 h2 = yh[i2], l2 = yl[i2];
        __half2 h3 = yh[i3], l3 = yl[i3];
        float vl = a0l * (__low2float(h1) + __low2float(l1))
                 + a1l * (__low2float(h2) + __low2float(l2))
                 + a2l * (__low2float(h3) + __low2float(l3));
        float vh = a0h * (__high2float(h1) + __high2float(l1))
                 + a1h * (__high2float(h2) + __high2float(l2))
                 + a2h * (__high2float(h3) + __high2float(l3));
        oc[(size_t)hw * (NF / 2) + tp] = __half2{__float2half_rn(vl), __float2half_rn(vh)};
    }
}

// ---------------- launch ----------------
extern "C" void kernel_launch(void* const* d_in, const int* in_sizes, int n_in,
                              void* d_out, int out_size) {
    const float* x   = (const float*)d_in[0];
    const float* W1  = (const float*)d_in[1];
    const float* b1  = (const float*)d_in[2];
    const float* Wg1 = (const float*)d_in[3];
    const float* Wg2 = (const float*)d_in[4];
    const float* W2  = (const float*)d_in[5];
    const float* b2  = (const float*)d_in[6];
    float* out = (float*)d_out;

    __half *yh, *yl, *xh, *xl, *oc, *w1h, *w1l, *w2h, *w2l;
    cudaGetSymbolAddress((void**)&yh, g_yh);
    cudaGetSymbolAddress((void**)&yl, g_yl);
    cudaGetSymbolAddress((void**)&xh, g_xh);
    cudaGetSymbolAddress((void**)&xl, g_xl);
    cudaGetSymbolAddress((void**)&oc, g_oc);
    cudaGetSymbolAddress((void**)&w1h, g_w1h);
    cudaGetSymbolAddress((void**)&w1l, g_w1l);
    cudaGetSymbolAddress((void**)&w2h, g_w2h);
    cudaGetSymbolAddress((void**)&w2l, g_w2l);

    cudaFuncSetAttribute(gemm1_f16x3,
                         cudaFuncAttributeMaxDynamicSharedMemorySize, G1_SMEM);
    cudaFuncSetAttribute(gemm2_f16x2,
                         cudaFuncAttributeMaxDynamicSharedMemorySize, G2_SMEM);

    splitx_kernel<<<(NROW * CIN / 4 + 255) / 256, 256>>>(x, xh, xl, NROW * CIN / 4);
    wsplit_kernel<<<dim3(D1 / 32, CIN / 32), dim3(32, 8)>>>(W1, w1h, w1l, CIN, D1);
    wsplit_kernel<<<dim3(NF / 32, NF / 32), dim3(32, 8)>>>(W2, w2h, w2l, NF, NF);

    gemm1_f16x3<<<dim3(D1 / BN, NROW / BM), 256, G1_SMEM>>>(
        xh, xl, w1h, w1l, b1, yh, yl, NROW, D1, CIN);

    reduce_a_kernel<<<dim3(HW / 64, Bn), 192>>>();
    gating_kernel<<<Bn, 768>>>(Wg1, Wg2);
    combine_kernel<<<dim3(HW / 64, Bn), 192>>>();

    gemm2_f16x2<<<dim3(NF / BN, NROW / BM), 256, G2_SMEM>>>(
        oc, w2h, w2l, b2, out, NROW, NF, NF);
}